// round 4
// baseline (speedup 1.0000x reference)
#include <cuda_runtime.h>
#include <cstdint>

#define S    1024
#define CD   64
#define DD   256
#define FD   512
#define BNT  32

// Scratch
__device__ __align__(256) float g_xth[BNT * S * CD];
__device__ __align__(256) float g_xtl[BNT * S * CD];
__device__ __align__(256) float g_t  [BNT * S * DD];
__device__ __align__(256) float g_tT [BNT * S * DD];
__device__ __align__(256) float g_tnh[BNT * S * DD];   // tn hi; reused as hn after scores
__device__ __align__(256) float g_tnl[BNT * S * DD];   // tn lo
__device__ __align__(256) float g_p  [(long)BNT * S * S];
__device__ __align__(256) float g_yh [BNT * S * DD];   // att, then y hi
__device__ __align__(256) float g_yl [BNT * S * DD];   // y lo
__device__ __align__(256) float g_hf [BNT * S * FD];
__device__ __align__(256) float g_wih[DD * CD];
__device__ __align__(256) float g_wil[DD * CD];
__device__ __align__(256) float g_woh[CD * DD];
__device__ __align__(256) float g_wol[CD * DD];

// ---------------------------------------------------------------------------
__device__ __forceinline__ float tf32r(float x) {
    uint32_t u;
    asm("cvt.rna.tf32.f32 %0, %1;" : "=r"(u) : "f"(x));
    return __uint_as_float(u);
}

#define MMA_TF32(d, a0, a1, a2, a3, b0, b1)                                   \
    asm volatile("mma.sync.aligned.m16n8k8.row.col.f32.tf32.tf32.f32 "        \
                 "{%0,%1,%2,%3}, {%4,%5,%6,%7}, {%8,%9}, {%0,%1,%2,%3};\n"    \
                 : "+f"(d[0]), "+f"(d[1]), "+f"(d[2]), "+f"(d[3])             \
                 : "r"(a0), "r"(a1), "r"(a2), "r"(a3), "r"(b0), "r"(b1))

#define UF(x) __float_as_uint(x)

__device__ __forceinline__ int sw_addr(int m, int q) {
    return m * 16 + (((q ^ ((m >> 1) & 3)) & 3) << 2);
}

// ---------------------------------------------------------------------------
// tf32 mma GEMM, double-buffered smem (one sync per k-tile).
// SPLIT : 0 single-pass tf32 (cvt hi in loader)
//         1 3xTF32, cvt in loader
//         2 3xTF32, hi/lo precomputed in gmem (Al_/Bl_)
// EPI   : 0 store, 1 relu, 2 +R, 3 scatter to out layout, 4 +R then hi/lo split
// CAUSAL: 1 tile skip (scores), 2 K limited to m0+128 (P@V)
// ---------------------------------------------------------------------------
template<int SPLIT, int EPI, int CAUSAL>
__global__ __launch_bounds__(256, (SPLIT != 0) ? 1 : 2)
void mma_gemm(const float* __restrict__ A, const float* __restrict__ Al_,
              long sAbn, int lda,
              const float* __restrict__ B, const float* __restrict__ Bl_,
              long sBbn, int ldb,
              float* __restrict__ C, float* __restrict__ C2, long sCbn, int ldc,
              const float* __restrict__ R, long sRbn,
              float* __restrict__ Op, int K)
{
    const int bx = blockIdx.x, by = blockIdx.y, bz = blockIdx.z;
    if (CAUSAL == 1 && bx > 2 * by + 1) return;

    constexpr int SS = (SPLIT != 0) ? 6144 : 3072;  // floats per stage
    __shared__ __align__(16) float sh[2 * SS];

    const int tid = threadIdx.x;
    const int w = tid >> 5, l = tid & 31;
    const int warp_m = (w & 3) * 32, warp_n = (w >> 2) * 32;
    const int g = l >> 2, cc = l & 3;
    const int m0 = by * 128, n0 = bx * 64;

    const float* Ab  = A + (long)bz * sAbn;
    const float* Bb  = B + (long)bz * sBbn;
    const float* Abl = (SPLIT == 2) ? (Al_ + (long)bz * sAbn) : nullptr;
    const float* Bbl = (SPLIT == 2) ? (Bl_ + (long)bz * sBbn) : nullptr;

    int Keff = K;
    if (CAUSAL == 2) { int lim = m0 + 128; if (lim < Keff) Keff = lim; }
    const int nk = Keff >> 4;

    const int am = tid >> 2, aj = tid & 3;
    const long offA0 = (long)(m0 + am)      * lda + aj * 4;
    const long offA1 = (long)(m0 + am + 64) * lda + aj * 4;
    const long offB  = (long)(n0 + am)      * ldb + aj * 4;

    float acc[2][4][4] = {};

    float4 ra0, ra1, rb, la0, la1, lb;
    ra0 = *(const float4*)(Ab + offA0);
    ra1 = *(const float4*)(Ab + offA1);
    rb  = *(const float4*)(Bb + offB);
    if (SPLIT == 2) {
        la0 = *(const float4*)(Abl + offA0);
        la1 = *(const float4*)(Abl + offA1);
        lb  = *(const float4*)(Bbl + offB);
    }

    auto store_stage = [&](int st) {
        float* sAhi = sh + st * SS;
        float* sBhi = sAhi + 2048;
        float* sAlo = sAhi + 3072;
        float* sBlo = sAhi + 5120;
        float va[4] = {ra0.x, ra0.y, ra0.z, ra0.w};
        float vb[4] = {ra1.x, ra1.y, ra1.z, ra1.w};
        float vc[4] = {rb.x,  rb.y,  rb.z,  rb.w};
        float xa[4], xb[4], xc[4];
        if (SPLIT == 2) {
            xa[0]=la0.x; xa[1]=la0.y; xa[2]=la0.z; xa[3]=la0.w;
            xb[0]=la1.x; xb[1]=la1.y; xb[2]=la1.z; xb[3]=la1.w;
            xc[0]=lb.x;  xc[1]=lb.y;  xc[2]=lb.z;  xc[3]=lb.w;
        }
        #pragma unroll
        for (int r = 0; r < 4; r++) {
            int ia = sw_addr(am, r) + aj;
            int ib = sw_addr(am + 64, r) + aj;
            int ic = sw_addr(am, r) + aj;
            if (SPLIT == 0) {
                sAhi[ia] = tf32r(va[r]); sAhi[ib] = tf32r(vb[r]); sBhi[ic] = tf32r(vc[r]);
            } else if (SPLIT == 1) {
                float ha = tf32r(va[r]), hb = tf32r(vb[r]), hc = tf32r(vc[r]);
                sAhi[ia] = ha; sAhi[ib] = hb; sBhi[ic] = hc;
                sAlo[ia] = tf32r(va[r] - ha);
                sAlo[ib] = tf32r(vb[r] - hb);
                sBlo[ic] = tf32r(vc[r] - hc);
            } else {
                sAhi[ia] = va[r]; sAhi[ib] = vb[r]; sBhi[ic] = vc[r];
                sAlo[ia] = xa[r]; sAlo[ib] = xb[r]; sBlo[ic] = xc[r];
            }
        }
    };

    store_stage(0);
    __syncthreads();

    for (int kt = 0; kt < nk; kt++) {
        const int st = kt & 1;
        if (kt + 1 < nk) {
            const long o = (long)(kt + 1) * 16;
            ra0 = *(const float4*)(Ab + offA0 + o);
            ra1 = *(const float4*)(Ab + offA1 + o);
            rb  = *(const float4*)(Bb + offB  + o);
            if (SPLIT == 2) {
                la0 = *(const float4*)(Abl + offA0 + o);
                la1 = *(const float4*)(Abl + offA1 + o);
                lb  = *(const float4*)(Bbl + offB  + o);
            }
        }

        float* sAhi = sh + st * SS;
        float* sBhi = sAhi + 2048;
        float* sAlo = sAhi + 3072;
        float* sBlo = sAhi + 5120;

        float4 Ah[2][2], Bh[4], Al[2][2], Bl[4];
        #pragma unroll
        for (int mi = 0; mi < 2; mi++) {
            int mr = warp_m + mi * 16 + g;
            Ah[mi][0] = *(const float4*)&sAhi[sw_addr(mr, cc)];
            Ah[mi][1] = *(const float4*)&sAhi[sw_addr(mr + 8, cc)];
            if (SPLIT) {
                Al[mi][0] = *(const float4*)&sAlo[sw_addr(mr, cc)];
                Al[mi][1] = *(const float4*)&sAlo[sw_addr(mr + 8, cc)];
            }
        }
        #pragma unroll
        for (int nj = 0; nj < 4; nj++) {
            int nr = warp_n + nj * 8 + g;
            Bh[nj] = *(const float4*)&sBhi[sw_addr(nr, cc)];
            if (SPLIT) Bl[nj] = *(const float4*)&sBlo[sw_addr(nr, cc)];
        }

        #pragma unroll
        for (int mi = 0; mi < 2; mi++) {
            #pragma unroll
            for (int nj = 0; nj < 4; nj++) {
                float* d = acc[mi][nj];
                MMA_TF32(d, UF(Ah[mi][0].x), UF(Ah[mi][1].x), UF(Ah[mi][0].y), UF(Ah[mi][1].y),
                            UF(Bh[nj].x), UF(Bh[nj].y));
                if (SPLIT) {
                    MMA_TF32(d, UF(Ah[mi][0].x), UF(Ah[mi][1].x), UF(Ah[mi][0].y), UF(Ah[mi][1].y),
                                UF(Bl[nj].x), UF(Bl[nj].y));
                    MMA_TF32(d, UF(Al[mi][0].x), UF(Al[mi][1].x), UF(Al[mi][0].y), UF(Al[mi][1].y),
                                UF(Bh[nj].x), UF(Bh[nj].y));
                }
                MMA_TF32(d, UF(Ah[mi][0].z), UF(Ah[mi][1].z), UF(Ah[mi][0].w), UF(Ah[mi][1].w),
                            UF(Bh[nj].z), UF(Bh[nj].w));
                if (SPLIT) {
                    MMA_TF32(d, UF(Ah[mi][0].z), UF(Ah[mi][1].z), UF(Ah[mi][0].w), UF(Ah[mi][1].w),
                                UF(Bl[nj].z), UF(Bl[nj].w));
                    MMA_TF32(d, UF(Al[mi][0].z), UF(Al[mi][1].z), UF(Al[mi][0].w), UF(Al[mi][1].w),
                                UF(Bh[nj].z), UF(Bh[nj].w));
                }
            }
        }

        if (kt + 1 < nk) {
            store_stage((kt + 1) & 1);
            __syncthreads();
        }
    }

    // ---- epilogue ----
    if (EPI == 3) {
        const int b = bz >> 3, n = bz & 7;
        #pragma unroll
        for (int mi = 0; mi < 2; mi++) {
            #pragma unroll
            for (int nj = 0; nj < 4; nj++) {
                int row = m0 + warp_m + mi * 16 + g;
                int col = n0 + warp_n + nj * 8 + 2 * cc;
                Op[((long)(b * 64 + col)     * 8 + n) * 1024 + row]     = acc[mi][nj][0];
                Op[((long)(b * 64 + col + 1) * 8 + n) * 1024 + row]     = acc[mi][nj][1];
                Op[((long)(b * 64 + col)     * 8 + n) * 1024 + row + 8] = acc[mi][nj][2];
                Op[((long)(b * 64 + col + 1) * 8 + n) * 1024 + row + 8] = acc[mi][nj][3];
            }
        }
    } else {
        float* Cb  = C + (long)bz * sCbn;
        float* C2b = (EPI == 4) ? (C2 + (long)bz * sCbn) : nullptr;
        const float* Rb = (EPI == 2 || EPI == 4) ? (R + (long)bz * sRbn) : nullptr;
        #pragma unroll
        for (int mi = 0; mi < 2; mi++) {
            #pragma unroll
            for (int nj = 0; nj < 4; nj++) {
                int row = m0 + warp_m + mi * 16 + g;
                int col = n0 + warp_n + nj * 8 + 2 * cc;
                float v[4] = {acc[mi][nj][0], acc[mi][nj][1], acc[mi][nj][2], acc[mi][nj][3]};
                if (EPI == 1) {
                    #pragma unroll
                    for (int q = 0; q < 4; q++) v[q] = fmaxf(v[q], 0.f);
                }
                if (EPI == 2 || EPI == 4) {
                    float2 r0 = *(const float2*)(Rb + (long)row * ldc + col);
                    float2 r1 = *(const float2*)(Rb + (long)(row + 8) * ldc + col);
                    v[0] += r0.x; v[1] += r0.y; v[2] += r1.x; v[3] += r1.y;
                }
                if (EPI == 4) {
                    float h[4], lo[4];
                    #pragma unroll
                    for (int q = 0; q < 4; q++) { h[q] = tf32r(v[q]); lo[q] = tf32r(v[q] - h[q]); }
                    *(float2*)(Cb  + (long)row * ldc + col)       = make_float2(h[0], h[1]);
                    *(float2*)(Cb  + (long)(row + 8) * ldc + col) = make_float2(h[2], h[3]);
                    *(float2*)(C2b + (long)row * ldc + col)       = make_float2(lo[0], lo[1]);
                    *(float2*)(C2b + (long)(row + 8) * ldc + col) = make_float2(lo[2], lo[3]);
                } else {
                    *(float2*)(Cb + (long)row * ldc + col)       = make_float2(v[0], v[1]);
                    *(float2*)(Cb + (long)(row + 8) * ldc + col) = make_float2(v[2], v[3]);
                }
            }
        }
    }
}

// ---------------------------------------------------------------------------
__global__ __launch_bounds__(256)
void wsplit_k(const float* __restrict__ w, float* __restrict__ hi,
              float* __restrict__ lo, int n)
{
    int i = blockIdx.x * 256 + threadIdx.x;
    if (i < n) {
        float v = w[i];
        float h = tf32r(v);
        hi[i] = h;
        lo[i] = tf32r(v - h);
    }
}

__global__ __launch_bounds__(256)
void transpose_x_k(const float* __restrict__ x, float* __restrict__ xth,
                   float* __restrict__ xtl)
{
    __shared__ float tile[32][33];
    int tx = threadIdx.x & 31, ty = threadIdx.x >> 5;
    int bn = blockIdx.z, b = bn >> 3, n = bn & 7;
    int s0 = blockIdx.x * 32, c0 = blockIdx.y * 32;
    const float* src = x + ((long)b * 64 * 8 + n) * 1024;
    #pragma unroll
    for (int i = 0; i < 4; i++)
        tile[ty + 8 * i][tx] = src[(long)(c0 + ty + 8 * i) * 8192 + s0 + tx];
    __syncthreads();
    float* dh = xth + (long)bn * (S * CD);
    float* dl = xtl + (long)bn * (S * CD);
    #pragma unroll
    for (int i = 0; i < 4; i++) {
        float v = tile[tx][ty + 8 * i];
        float h = tf32r(v);
        long idx = (long)(s0 + ty + 8 * i) * 64 + c0 + tx;
        dh[idx] = h;
        dl[idx] = tf32r(v - h);
    }
}

__global__ __launch_bounds__(256)
void transpose_t_k(const float* __restrict__ t, float* __restrict__ tT)
{
    __shared__ float tile[32][33];
    int tx = threadIdx.x & 31, ty = threadIdx.x >> 5;
    int bn = blockIdx.z;
    int s0 = blockIdx.x * 32, d0 = blockIdx.y * 32;
    const float* src = t + (long)bn * (S * DD);
    #pragma unroll
    for (int i = 0; i < 4; i++)
        tile[ty + 8 * i][tx] = src[(long)(s0 + ty + 8 * i) * 256 + d0 + tx];
    __syncthreads();
    float* dst = tT + (long)bn * (S * DD);
    #pragma unroll
    for (int i = 0; i < 4; i++)
        dst[(long)(d0 + ty + 8 * i) * 1024 + s0 + tx] = tile[tx][ty + 8 * i];
}

// ---------------------------------------------------------------------------
template<int WRITE_SPLIT>
__global__ __launch_bounds__(256)
void ln_k(const float* __restrict__ in, float* __restrict__ out,
          float* __restrict__ out_lo,
          const float* __restrict__ gam, const float* __restrict__ bet)
{
    int warp = (blockIdx.x * blockDim.x + threadIdx.x) >> 5;
    int lane = threadIdx.x & 31;
    const float* x = in + (long)warp * DD;

    float v[8], s = 0.f, ss = 0.f;
    #pragma unroll
    for (int i = 0; i < 8; i++) {
        v[i] = x[lane + 32 * i];
        s += v[i]; ss += v[i] * v[i];
    }
    #pragma unroll
    for (int o = 16; o; o >>= 1) {
        s  += __shfl_xor_sync(0xffffffffu, s,  o);
        ss += __shfl_xor_sync(0xffffffffu, ss, o);
    }
    float mu = s * (1.f / DD);
    float var = ss * (1.f / DD) - mu * mu;
    float rs = rsqrtf(var + 1e-5f);

    float* o_ = out + (long)warp * DD;
    float* ol = WRITE_SPLIT ? (out_lo + (long)warp * DD) : nullptr;
    #pragma unroll
    for (int i = 0; i < 8; i++) {
        int c = lane + 32 * i;
        float y = (v[i] - mu) * rs * gam[c] + bet[c];
        if (WRITE_SPLIT) {
            float h = tf32r(y);
            o_[c] = h;
            ol[c] = tf32r(y - h);
        } else {
            o_[c] = y;
        }
    }
}

// ---------------------------------------------------------------------------
__global__ __launch_bounds__(256)
void softmax_k(float* __restrict__ p)
{
    int warp = (blockIdx.x * blockDim.x + threadIdx.x) >> 5;
    int lane = threadIdx.x & 31;
    int q = warp & (S - 1);
    float* row = p + (long)warp * S;

    float v[32], mx = -3.4e38f;
    #pragma unroll
    for (int i = 0; i < 32; i++) {
        int col = lane + 32 * i;
        v[i] = (col <= q) ? row[col] : -3.4e38f;
        mx = fmaxf(mx, v[i]);
    }
    #pragma unroll
    for (int o = 16; o; o >>= 1) mx = fmaxf(mx, __shfl_xor_sync(0xffffffffu, mx, o));

    float sum = 0.f;
    #pragma unroll
    for (int i = 0; i < 32; i++) {
        int col = lane + 32 * i;
        v[i] = (col <= q) ? expf(v[i] - mx) : 0.f;
        sum += v[i];
    }
    #pragma unroll
    for (int o = 16; o; o >>= 1) sum += __shfl_xor_sync(0xffffffffu, sum, o);
    float inv = 1.f / sum;

    int kend = ((q >> 7) + 1) << 7;
    #pragma unroll
    for (int i = 0; i < 32; i++) {
        int col = lane + 32 * i;
        if (col < kend) row[col] = v[i] * inv;
    }
}

// ---------------------------------------------------------------------------
extern "C" void kernel_launch(void* const* d_in, const int* in_sizes, int n_in,
                              void* d_out, int out_size)
{
    (void)in_sizes; (void)n_in; (void)out_size;
    const float* buffer = (const float*)d_in[0];
    const float* W_in   = (const float*)d_in[1];
    const float* ln1_g  = (const float*)d_in[2];
    const float* ln1_b  = (const float*)d_in[3];
    const float* ln2_g  = (const float*)d_in[4];
    const float* ln2_b  = (const float*)d_in[5];
    const float* W1     = (const float*)d_in[6];
    const float* W2     = (const float*)d_in[7];
    const float* W_out  = (const float*)d_in[8];
    float* out = (float*)d_out;

    float *xth, *xtl, *t, *tT, *tnh, *tnl, *p, *yh, *yl, *hf;
    float *wih, *wil, *woh, *wol;
    cudaGetSymbolAddress((void**)&xth, g_xth);
    cudaGetSymbolAddress((void**)&xtl, g_xtl);
    cudaGetSymbolAddress((void**)&t,   g_t);
    cudaGetSymbolAddress((void**)&tT,  g_tT);
    cudaGetSymbolAddress((void**)&tnh, g_tnh);
    cudaGetSymbolAddress((void**)&tnl, g_tnl);
    cudaGetSymbolAddress((void**)&p,   g_p);
    cudaGetSymbolAddress((void**)&yh,  g_yh);
    cudaGetSymbolAddress((void**)&yl,  g_yl);
    cudaGetSymbolAddress((void**)&hf,  g_hf);
    cudaGetSymbolAddress((void**)&wih, g_wih);
    cudaGetSymbolAddress((void**)&wil, g_wil);
    cudaGetSymbolAddress((void**)&woh, g_woh);
    cudaGetSymbolAddress((void**)&wol, g_wol);

    const long sT = (long)S * DD;
    const long sP = (long)S * S;
    const long sH = (long)S * FD;
    const long sX = (long)S * CD;

    // weight splits (cheap)
    wsplit_k<<<(DD * CD + 255) / 256, 256>>>(W_in,  wih, wil, DD * CD);
    wsplit_k<<<(CD * DD + 255) / 256, 256>>>(W_out, woh, wol, CD * DD);

    // 0) transpose x -> xt hi/lo
    transpose_x_k<<<dim3(32, 2, BNT), 256>>>(buffer, xth, xtl);

    // 1) t = xt . W_in^T   (split, precomputed)
    mma_gemm<2, 0, 0><<<dim3(4, 8, BNT), 256>>>(
        xth, xtl, sX, CD,  wih, wil, 0, CD,
        t, nullptr, sT, DD,  nullptr, 0, nullptr, CD);

    // 2) tn = LN1(t), hi/lo
    ln_k<1><<<(BNT * S) / 8, 256>>>(t, tnh, tnl, ln1_g, ln1_b);

    // 3) scores = tn . tn^T  (split precomputed, causal tile skip)
    mma_gemm<2, 0, 1><<<dim3(16, 8, BNT), 256>>>(
        tnh, tnl, sT, DD,  tnh, tnl, sT, DD,
        p, nullptr, sP, S,  nullptr, 0, nullptr, DD);

    // 4) softmax
    softmax_k<<<(BNT * S) / 8, 256>>>(p);

    // 5) transpose t -> tT
    transpose_t_k<<<dim3(32, 8, BNT), 256>>>(t, tT);

    // 6) att = p . t + t    (single tf32, K limited)
    mma_gemm<0, 2, 2><<<dim3(4, 8, BNT), 256>>>(
        p, nullptr, sP, S,  tT, nullptr, sT, S,
        yh, nullptr, sT, DD,  t, sT, nullptr, S);

    // 7) hn = LN2(att) -> tnh (plain)
    ln_k<0><<<(BNT * S) / 8, 256>>>(yh, tnh, nullptr, ln2_g, ln2_b);

    // 8) hf = relu(hn . W1^T)
    mma_gemm<0, 1, 0><<<dim3(8, 8, BNT), 256>>>(
        tnh, nullptr, sT, DD,  W1, nullptr, 0, DD,
        hf, nullptr, sH, FD,  nullptr, 0, nullptr, DD);

    // 9) y = hf . W2^T + t  -> yh/yl (split epilogue)
    mma_gemm<0, 4, 0><<<dim3(4, 8, BNT), 256>>>(
        hf, nullptr, sH, FD,  W2, nullptr, 0, FD,
        yh, yl, sT, DD,  t, sT, nullptr, FD);

    // 10) out = y . W_out^T (split precomputed, scatter epilogue)
    mma_gemm<2, 3, 0><<<dim3(1, 8, BNT), 256>>>(
        yh, yl, sT, DD,  woh, wol, 0, DD,
        nullptr, nullptr, 0, 0,  nullptr, 0, out, DD);
}

// round 5
// speedup vs baseline: 1.2944x; 1.2944x over previous
#include <cuda_runtime.h>
#include <cstdint>

#define S    1024
#define CD   64
#define DD   256
#define FD   512
#define BNT  32

// Scratch
__device__ __align__(256) float g_xth[BNT * S * CD];
__device__ __align__(256) float g_xtl[BNT * S * CD];
__device__ __align__(256) float g_t  [BNT * S * DD];
__device__ __align__(256) float g_tT [BNT * S * DD];
__device__ __align__(256) float g_tnh[BNT * S * DD];   // tn hi; reused as hn
__device__ __align__(256) float g_tnl[BNT * S * DD];
__device__ __align__(256) float g_p  [(long)BNT * S * S];
__device__ __align__(256) float g_yh [BNT * S * DD];   // att, then y hi
__device__ __align__(256) float g_yl [BNT * S * DD];
__device__ __align__(256) float g_hf [BNT * S * FD];
__device__ __align__(256) float g_wih[DD * CD];
__device__ __align__(256) float g_wil[DD * CD];
__device__ __align__(256) float g_woh[CD * DD];
__device__ __align__(256) float g_wol[CD * DD];
__device__ __align__(256) float g_w1p[FD * DD];
__device__ __align__(256) float g_w2p[DD * FD];

// ---------------------------------------------------------------------------
__device__ __forceinline__ float tf32r(float x) {
    uint32_t u;
    asm("cvt.rna.tf32.f32 %0, %1;" : "=r"(u) : "f"(x));
    return __uint_as_float(u);
}

// k-permutation within 16-blocks (involution): k' = (k&3)*4 + (k>>2)&3
__device__ __forceinline__ int kperm(int k) {
    return (k & ~15) | ((k & 3) << 2) | ((k >> 2) & 3);
}

#define MMA_TF32(d, a0, a1, a2, a3, b0, b1)                                   \
    asm volatile("mma.sync.aligned.m16n8k8.row.col.f32.tf32.tf32.f32 "        \
                 "{%0,%1,%2,%3}, {%4,%5,%6,%7}, {%8,%9}, {%0,%1,%2,%3};\n"    \
                 : "+f"(d[0]), "+f"(d[1]), "+f"(d[2]), "+f"(d[3])             \
                 : "r"(a0), "r"(a1), "r"(a2), "r"(a3), "r"(b0), "r"(b1))

#define UF(x) __float_as_uint(x)

#define CP16(dst, src)                                                        \
    asm volatile("cp.async.cg.shared.global [%0], [%1], 16;\n"                \
                 :: "r"(dst), "l"(src))

// read-side swizzled word address (same layout as before; chunk-level swizzle)
__device__ __forceinline__ int sw_addr(int m, int q) {
    return m * 16 + (((q ^ ((m >> 1) & 3)) & 3) << 2);
}

// ---------------------------------------------------------------------------
// tf32 mma GEMM: cp.async 3-stage pipeline, k-permuted gmem operands.
// SPLIT : 0 single-pass (raw fp32, HW truncation), 1 hi/lo precomputed in gmem
// EPI   : 0 store, 1 relu+perm-col store, 2 +R store, 3 scatter to out,
//         4 +R, hi/lo split, perm-col store
// CAUSAL: 1 tile skip (scores), 2 K limited to m0+128 (P@V)
// ---------------------------------------------------------------------------
template<int SPLIT, int EPI, int CAUSAL>
__global__ __launch_bounds__(256, 2)
void mma_gemm(const float* __restrict__ A, const float* __restrict__ Al_,
              long sAbn, int lda,
              const float* __restrict__ B, const float* __restrict__ Bl_,
              long sBbn, int ldb,
              float* __restrict__ C, float* __restrict__ C2, long sCbn, int ldc,
              const float* __restrict__ R, long sRbn,
              float* __restrict__ Op, int K)
{
    const int bx = blockIdx.x, by = blockIdx.y, bz = blockIdx.z;
    if (CAUSAL == 1 && bx > 2 * by + 1) return;

    constexpr int SS = SPLIT ? 6144 : 3072;   // floats per stage
    extern __shared__ __align__(16) float sh[];

    const int tid = threadIdx.x;
    const int w = tid >> 5, l = tid & 31;
    const int warp_m = (w & 3) * 32, warp_n = (w >> 2) * 32;
    const int g = l >> 2, cc = l & 3;
    const int m0 = by * 128, n0 = bx * 64;

    const float* Ab  = A + (long)bz * sAbn;
    const float* Bb  = B + (long)bz * sBbn;
    const float* Abl = SPLIT ? (Al_ + (long)bz * sAbn) : nullptr;
    const float* Bbl = SPLIT ? (Bl_ + (long)bz * sBbn) : nullptr;

    int Keff = K;
    if (CAUSAL == 2) { int lim = m0 + 128; if (lim < Keff) Keff = lim; }
    const int nk = Keff >> 4;

    const int am = tid >> 2, aj = tid & 3;
    const long oA0 = (long)(m0 + am)      * lda + aj * 4;
    const long oA1 = (long)(m0 + am + 64) * lda + aj * 4;
    const long oB  = (long)(n0 + am)      * ldb + aj * 4;
    const int swz  = ((aj ^ ((am >> 1) & 3)) & 3) << 2;
    const int slA0 = am * 16 + swz;
    const int slA1 = (am + 64) * 16 + swz;       // ((am+64)>>1)&3 == (am>>1)&3
    const int slB  = 2048 + am * 16 + swz;
    const uint32_t sb = (uint32_t)__cvta_generic_to_shared(sh);

    auto issue = [&](int st, int kt) {
        uint32_t s0 = sb + (uint32_t)(st * SS) * 4u;
        long ko = (long)kt * 16;
        CP16(s0 + slA0 * 4, Ab + oA0 + ko);
        CP16(s0 + slA1 * 4, Ab + oA1 + ko);
        CP16(s0 + slB  * 4, Bb + oB  + ko);
        if (SPLIT) {
            CP16(s0 + (slA0 + 3072) * 4, Abl + oA0 + ko);
            CP16(s0 + (slA1 + 3072) * 4, Abl + oA1 + ko);
            CP16(s0 + (slB  + 3072) * 4, Bbl + oB  + ko);
        }
        asm volatile("cp.async.commit_group;\n" ::);
    };

    float acc[2][4][4] = {};

    issue(0, 0);
    if (nk > 1) issue(1, 1);
    else        asm volatile("cp.async.commit_group;\n" ::);

    for (int kt = 0; kt < nk; kt++) {
        asm volatile("cp.async.wait_group 1;\n" ::);
        __syncthreads();
        if (kt + 2 < nk) issue((kt + 2) % 3, kt + 2);
        else             asm volatile("cp.async.commit_group;\n" ::);

        const float* sAhi = sh + (kt % 3) * SS;
        const float* sBhi = sAhi + 2048;
        const float* sAlo = sAhi + 3072;
        const float* sBlo = sAhi + 5120;

        float4 Ah[2][2], Bh[4], Al[2][2], Bl[4];
        #pragma unroll
        for (int mi = 0; mi < 2; mi++) {
            int mr = warp_m + mi * 16 + g;
            Ah[mi][0] = *(const float4*)&sAhi[sw_addr(mr, cc)];
            Ah[mi][1] = *(const float4*)&sAhi[sw_addr(mr + 8, cc)];
            if (SPLIT) {
                Al[mi][0] = *(const float4*)&sAlo[sw_addr(mr, cc)];
                Al[mi][1] = *(const float4*)&sAlo[sw_addr(mr + 8, cc)];
            }
        }
        #pragma unroll
        for (int nj = 0; nj < 4; nj++) {
            int nr = warp_n + nj * 8 + g;
            Bh[nj] = *(const float4*)&sBhi[sw_addr(nr, cc)];
            if (SPLIT) Bl[nj] = *(const float4*)&sBlo[sw_addr(nr, cc)];
        }

        #pragma unroll
        for (int mi = 0; mi < 2; mi++) {
            #pragma unroll
            for (int nj = 0; nj < 4; nj++) {
                float* d = acc[mi][nj];
                MMA_TF32(d, UF(Ah[mi][0].x), UF(Ah[mi][1].x), UF(Ah[mi][0].y), UF(Ah[mi][1].y),
                            UF(Bh[nj].x), UF(Bh[nj].y));
                if (SPLIT) {
                    MMA_TF32(d, UF(Ah[mi][0].x), UF(Ah[mi][1].x), UF(Ah[mi][0].y), UF(Ah[mi][1].y),
                                UF(Bl[nj].x), UF(Bl[nj].y));
                    MMA_TF32(d, UF(Al[mi][0].x), UF(Al[mi][1].x), UF(Al[mi][0].y), UF(Al[mi][1].y),
                                UF(Bh[nj].x), UF(Bh[nj].y));
                }
                MMA_TF32(d, UF(Ah[mi][0].z), UF(Ah[mi][1].z), UF(Ah[mi][0].w), UF(Ah[mi][1].w),
                            UF(Bh[nj].z), UF(Bh[nj].w));
                if (SPLIT) {
                    MMA_TF32(d, UF(Ah[mi][0].z), UF(Ah[mi][1].z), UF(Ah[mi][0].w), UF(Ah[mi][1].w),
                                UF(Bl[nj].z), UF(Bl[nj].w));
                    MMA_TF32(d, UF(Al[mi][0].z), UF(Al[mi][1].z), UF(Al[mi][0].w), UF(Al[mi][1].w),
                                UF(Bh[nj].z), UF(Bh[nj].w));
                }
            }
        }
    }

    // ---- epilogue ----
    if (EPI == 3) {
        const int b = bz >> 3, n = bz & 7;
        #pragma unroll
        for (int mi = 0; mi < 2; mi++) {
            #pragma unroll
            for (int nj = 0; nj < 4; nj++) {
                int row = m0 + warp_m + mi * 16 + g;
                int col = n0 + warp_n + nj * 8 + 2 * cc;
                Op[((long)(b * 64 + col)     * 8 + n) * 1024 + row]     = acc[mi][nj][0];
                Op[((long)(b * 64 + col + 1) * 8 + n) * 1024 + row]     = acc[mi][nj][1];
                Op[((long)(b * 64 + col)     * 8 + n) * 1024 + row + 8] = acc[mi][nj][2];
                Op[((long)(b * 64 + col + 1) * 8 + n) * 1024 + row + 8] = acc[mi][nj][3];
            }
        }
    } else if (EPI == 1) {
        float* Cb = C + (long)bz * sCbn;
        #pragma unroll
        for (int mi = 0; mi < 2; mi++) {
            #pragma unroll
            for (int nj = 0; nj < 4; nj++) {
                int row = m0 + warp_m + mi * 16 + g;
                int col = n0 + warp_n + nj * 8 + 2 * cc;
                int p0 = kperm(col), p1 = kperm(col + 1);
                Cb[(long)row * ldc + p0]       = fmaxf(acc[mi][nj][0], 0.f);
                Cb[(long)row * ldc + p1]       = fmaxf(acc[mi][nj][1], 0.f);
                Cb[(long)(row + 8) * ldc + p0] = fmaxf(acc[mi][nj][2], 0.f);
                Cb[(long)(row + 8) * ldc + p1] = fmaxf(acc[mi][nj][3], 0.f);
            }
        }
    } else if (EPI == 4) {
        float* Cb  = C  + (long)bz * sCbn;
        float* C2b = C2 + (long)bz * sCbn;
        const float* Rb = R + (long)bz * sRbn;
        #pragma unroll
        for (int mi = 0; mi < 2; mi++) {
            #pragma unroll
            for (int nj = 0; nj < 4; nj++) {
                int row = m0 + warp_m + mi * 16 + g;
                int col = n0 + warp_n + nj * 8 + 2 * cc;
                int p0 = kperm(col), p1 = kperm(col + 1);
                float2 r0 = *(const float2*)(Rb + (long)row * ldc + col);
                float2 r1 = *(const float2*)(Rb + (long)(row + 8) * ldc + col);
                float v[4] = {acc[mi][nj][0] + r0.x, acc[mi][nj][1] + r0.y,
                              acc[mi][nj][2] + r1.x, acc[mi][nj][3] + r1.y};
                float h[4], lo[4];
                #pragma unroll
                for (int q = 0; q < 4; q++) { h[q] = tf32r(v[q]); lo[q] = tf32r(v[q] - h[q]); }
                Cb [(long)row * ldc + p0]       = h[0];
                Cb [(long)row * ldc + p1]       = h[1];
                Cb [(long)(row + 8) * ldc + p0] = h[2];
                Cb [(long)(row + 8) * ldc + p1] = h[3];
                C2b[(long)row * ldc + p0]       = lo[0];
                C2b[(long)row * ldc + p1]       = lo[1];
                C2b[(long)(row + 8) * ldc + p0] = lo[2];
                C2b[(long)(row + 8) * ldc + p1] = lo[3];
            }
        }
    } else {
        float* Cb = C + (long)bz * sCbn;
        const float* Rb = (EPI == 2) ? (R + (long)bz * sRbn) : nullptr;
        #pragma unroll
        for (int mi = 0; mi < 2; mi++) {
            #pragma unroll
            for (int nj = 0; nj < 4; nj++) {
                int row = m0 + warp_m + mi * 16 + g;
                int col = n0 + warp_n + nj * 8 + 2 * cc;
                float v[4] = {acc[mi][nj][0], acc[mi][nj][1], acc[mi][nj][2], acc[mi][nj][3]};
                if (EPI == 2) {
                    float2 r0 = *(const float2*)(Rb + (long)row * ldc + col);
                    float2 r1 = *(const float2*)(Rb + (long)(row + 8) * ldc + col);
                    v[0] += r0.x; v[1] += r0.y; v[2] += r1.x; v[3] += r1.y;
                }
                *(float2*)(Cb + (long)row * ldc + col)       = make_float2(v[0], v[1]);
                *(float2*)(Cb + (long)(row + 8) * ldc + col) = make_float2(v[2], v[3]);
            }
        }
    }
}

// ---------------------------------------------------------------------------
__global__ __launch_bounds__(256)
void wsplit_k(const float* __restrict__ w, float* __restrict__ hi,
              float* __restrict__ lo, int n, int Kd)
{
    int i = blockIdx.x * 256 + threadIdx.x;
    if (i < n) {
        int row = i / Kd, k = i % Kd;
        int o = row * Kd + kperm(k);
        float v = w[i];
        float h = tf32r(v);
        hi[o] = h;
        lo[o] = tf32r(v - h);
    }
}

__global__ __launch_bounds__(256)
void wperm_k(const float* __restrict__ w, float* __restrict__ o_, int n, int Kd)
{
    int i = blockIdx.x * 256 + threadIdx.x;
    if (i < n) {
        int row = i / Kd, k = i % Kd;
        o_[row * Kd + kperm(k)] = w[i];
    }
}

__global__ __launch_bounds__(256)
void transpose_x_k(const float* __restrict__ x, float* __restrict__ xth,
                   float* __restrict__ xtl)
{
    __shared__ float tile[32][33];
    int tx = threadIdx.x & 31, ty = threadIdx.x >> 5;
    int bn = blockIdx.z, b = bn >> 3, n = bn & 7;
    int s0 = blockIdx.x * 32, c0 = blockIdx.y * 32;
    const float* src = x + ((long)b * 64 * 8 + n) * 1024;
    #pragma unroll
    for (int i = 0; i < 4; i++)
        tile[ty + 8 * i][tx] = src[(long)(c0 + ty + 8 * i) * 8192 + s0 + tx];
    __syncthreads();
    float* dh = xth + (long)bn * (S * CD);
    float* dl = xtl + (long)bn * (S * CD);
    int pc = kperm(c0 + tx);
    #pragma unroll
    for (int i = 0; i < 4; i++) {
        float v = tile[tx][ty + 8 * i];
        float h = tf32r(v);
        long idx = (long)(s0 + ty + 8 * i) * 64 + pc;
        dh[idx] = h;
        dl[idx] = tf32r(v - h);
    }
}

__global__ __launch_bounds__(256)
void transpose_t_k(const float* __restrict__ t, float* __restrict__ tT)
{
    __shared__ float tile[32][33];
    int tx = threadIdx.x & 31, ty = threadIdx.x >> 5;
    int bn = blockIdx.z;
    int s0 = blockIdx.x * 32, d0 = blockIdx.y * 32;
    const float* src = t + (long)bn * (S * DD);
    #pragma unroll
    for (int i = 0; i < 4; i++)
        tile[ty + 8 * i][tx] = src[(long)(s0 + ty + 8 * i) * 256 + d0 + tx];
    __syncthreads();
    float* dst = tT + (long)bn * (S * DD);
    int ps = kperm(s0 + tx);
    #pragma unroll
    for (int i = 0; i < 4; i++)
        dst[(long)(d0 + ty + 8 * i) * 1024 + ps] = tile[tx][ty + 8 * i];
}

// ---------------------------------------------------------------------------
template<int WRITE_SPLIT>
__global__ __launch_bounds__(256)
void ln_k(const float* __restrict__ in, float* __restrict__ out,
          float* __restrict__ out_lo,
          const float* __restrict__ gam, const float* __restrict__ bet)
{
    int warp = (blockIdx.x * blockDim.x + threadIdx.x) >> 5;
    int lane = threadIdx.x & 31;
    const float* x = in + (long)warp * DD;

    float v[8], s = 0.f, ss = 0.f;
    #pragma unroll
    for (int i = 0; i < 8; i++) {
        v[i] = x[lane + 32 * i];
        s += v[i]; ss += v[i] * v[i];
    }
    #pragma unroll
    for (int o = 16; o; o >>= 1) {
        s  += __shfl_xor_sync(0xffffffffu, s,  o);
        ss += __shfl_xor_sync(0xffffffffu, ss, o);
    }
    float mu = s * (1.f / DD);
    float var = ss * (1.f / DD) - mu * mu;
    float rs = rsqrtf(var + 1e-5f);

    float* o_ = out + (long)warp * DD;
    float* ol = WRITE_SPLIT ? (out_lo + (long)warp * DD) : nullptr;
    #pragma unroll
    for (int i = 0; i < 8; i++) {
        int c = lane + 32 * i;
        int pc = kperm(c);
        float y = (v[i] - mu) * rs * gam[c] + bet[c];
        if (WRITE_SPLIT) {
            float h = tf32r(y);
            o_[pc] = h;
            ol[pc] = tf32r(y - h);
        } else {
            o_[pc] = y;
        }
    }
}

// ---------------------------------------------------------------------------
__global__ __launch_bounds__(256)
void softmax_k(float* __restrict__ p)
{
    int warp = (blockIdx.x * blockDim.x + threadIdx.x) >> 5;
    int lane = threadIdx.x & 31;
    int q = warp & (S - 1);
    float* row = p + (long)warp * S;

    float v[32], mx = -3.4e38f;
    #pragma unroll
    for (int i = 0; i < 32; i++) {
        int col = lane + 32 * i;
        v[i] = (col <= q) ? row[col] : -3.4e38f;
        mx = fmaxf(mx, v[i]);
    }
    #pragma unroll
    for (int o = 16; o; o >>= 1) mx = fmaxf(mx, __shfl_xor_sync(0xffffffffu, mx, o));

    float sum = 0.f;
    #pragma unroll
    for (int i = 0; i < 32; i++) {
        int col = lane + 32 * i;
        v[i] = (col <= q) ? expf(v[i] - mx) : 0.f;
        sum += v[i];
    }
    #pragma unroll
    for (int o = 16; o; o >>= 1) sum += __shfl_xor_sync(0xffffffffu, sum, o);
    float inv = 1.f / sum;

    int kend = ((q >> 7) + 1) << 7;
    #pragma unroll
    for (int i = 0; i < 32; i++) {
        int col = lane + 32 * i;
        if (col < kend) row[kperm(col)] = v[i] * inv;
    }
}

// ---------------------------------------------------------------------------
extern "C" void kernel_launch(void* const* d_in, const int* in_sizes, int n_in,
                              void* d_out, int out_size)
{
    (void)in_sizes; (void)n_in; (void)out_size;
    const float* buffer = (const float*)d_in[0];
    const float* W_in   = (const float*)d_in[1];
    const float* ln1_g  = (const float*)d_in[2];
    const float* ln1_b  = (const float*)d_in[3];
    const float* ln2_g  = (const float*)d_in[4];
    const float* ln2_b  = (const float*)d_in[5];
    const float* W1     = (const float*)d_in[6];
    const float* W2     = (const float*)d_in[7];
    const float* W_out  = (const float*)d_in[8];
    float* out = (float*)d_out;

    float *xth, *xtl, *t, *tT, *tnh, *tnl, *p, *yh, *yl, *hf;
    float *wih, *wil, *woh, *wol, *w1p, *w2p;
    cudaGetSymbolAddress((void**)&xth, g_xth);
    cudaGetSymbolAddress((void**)&xtl, g_xtl);
    cudaGetSymbolAddress((void**)&t,   g_t);
    cudaGetSymbolAddress((void**)&tT,  g_tT);
    cudaGetSymbolAddress((void**)&tnh, g_tnh);
    cudaGetSymbolAddress((void**)&tnl, g_tnl);
    cudaGetSymbolAddress((void**)&p,   g_p);
    cudaGetSymbolAddress((void**)&yh,  g_yh);
    cudaGetSymbolAddress((void**)&yl,  g_yl);
    cudaGetSymbolAddress((void**)&hf,  g_hf);
    cudaGetSymbolAddress((void**)&wih, g_wih);
    cudaGetSymbolAddress((void**)&wil, g_wil);
    cudaGetSymbolAddress((void**)&woh, g_woh);
    cudaGetSymbolAddress((void**)&wol, g_wol);
    cudaGetSymbolAddress((void**)&w1p, g_w1p);
    cudaGetSymbolAddress((void**)&w2p, g_w2p);

    const long sT = (long)S * DD;
    const long sP = (long)S * S;
    const long sH = (long)S * FD;
    const long sX = (long)S * CD;

    const int smem_split  = 3 * 6144 * 4;   // 73728 B
    const int smem_single = 3 * 3072 * 4;   // 36864 B
    cudaFuncSetAttribute(mma_gemm<1, 0, 0>, cudaFuncAttributeMaxDynamicSharedMemorySize, smem_split);
    cudaFuncSetAttribute(mma_gemm<1, 0, 1>, cudaFuncAttributeMaxDynamicSharedMemorySize, smem_split);
    cudaFuncSetAttribute(mma_gemm<1, 3, 0>, cudaFuncAttributeMaxDynamicSharedMemorySize, smem_split);
    cudaFuncSetAttribute(mma_gemm<0, 2, 2>, cudaFuncAttributeMaxDynamicSharedMemorySize, smem_single);
    cudaFuncSetAttribute(mma_gemm<0, 1, 0>, cudaFuncAttributeMaxDynamicSharedMemorySize, smem_single);
    cudaFuncSetAttribute(mma_gemm<0, 4, 0>, cudaFuncAttributeMaxDynamicSharedMemorySize, smem_single);

    // weight prep (k-permuted; hi/lo for split operands)
    wsplit_k<<<(DD * CD + 255) / 256, 256>>>(W_in,  wih, wil, DD * CD, CD);
    wsplit_k<<<(CD * DD + 255) / 256, 256>>>(W_out, woh, wol, CD * DD, DD);
    wperm_k <<<(FD * DD + 255) / 256, 256>>>(W1, w1p, FD * DD, DD);
    wperm_k <<<(DD * FD + 255) / 256, 256>>>(W2, w2p, DD * FD, FD);

    // 0) transpose x -> xt hi/lo (c-permuted)
    transpose_x_k<<<dim3(32, 2, BNT), 256>>>(buffer, xth, xtl);

    // 1) t = xt . W_in^T   (split)
    mma_gemm<1, 0, 0><<<dim3(4, 8, BNT), 256, smem_split>>>(
        xth, xtl, sX, CD,  wih, wil, 0, CD,
        t, nullptr, sT, DD,  nullptr, 0, nullptr, CD);

    // 2) tn = LN1(t), hi/lo (d-permuted)
    ln_k<1><<<(BNT * S) / 8, 256>>>(t, tnh, tnl, ln1_g, ln1_b);

    // 3) scores = tn . tn^T  (split, causal tile skip)
    mma_gemm<1, 0, 1><<<dim3(16, 8, BNT), 256, smem_split>>>(
        tnh, tnl, sT, DD,  tnh, tnl, sT, DD,
        p, nullptr, sP, S,  nullptr, 0, nullptr, DD);

    // 4) softmax (writes k-permuted p)
    softmax_k<<<(BNT * S) / 8, 256>>>(p);

    // 5) transpose t -> tT (s-permuted)
    transpose_t_k<<<dim3(32, 8, BNT), 256>>>(t, tT);

    // 6) att = p . t + t    (single, K limited)
    mma_gemm<0, 2, 2><<<dim3(4, 8, BNT), 256, smem_single>>>(
        p, nullptr, sP, S,  tT, nullptr, sT, S,
        yh, nullptr, sT, DD,  t, sT, nullptr, S);

    // 7) hn = LN2(att) -> tnh (d-permuted)
    ln_k<0><<<(BNT * S) / 8, 256>>>(yh, tnh, nullptr, ln2_g, ln2_b);

    // 8) hf = relu(hn . W1^T)  (f-permuted output)
    mma_gemm<0, 1, 0><<<dim3(8, 8, BNT), 256, smem_single>>>(
        tnh, nullptr, sT, DD,  w1p, nullptr, 0, DD,
        hf, nullptr, sH, FD,  nullptr, 0, nullptr, DD);

    // 9) y = hf . W2^T + t  -> yh/yl (split, d-permuted output)
    mma_gemm<0, 4, 0><<<dim3(4, 8, BNT), 256, smem_single>>>(
        hf, nullptr, sH, FD,  w2p, nullptr, 0, FD,
        yh, yl, sT, DD,  t, sT, nullptr, FD);

    // 10) out = y . W_out^T (split, scatter epilogue)
    mma_gemm<1, 3, 0><<<dim3(1, 8, BNT), 256, smem_split>>>(
        yh, yl, sT, DD,  woh, wol, 0, DD,
        nullptr, nullptr, 0, 0,  nullptr, 0, out, DD);
}

// round 6
// speedup vs baseline: 1.3484x; 1.0417x over previous
#include <cuda_runtime.h>
#include <cstdint>

#define S    1024
#define CD   64
#define DD   256
#define FD   512
#define BNT  32

// Scratch
__device__ __align__(256) float g_xth[BNT * S * CD];
__device__ __align__(256) float g_xtl[BNT * S * CD];
__device__ __align__(256) float g_t  [BNT * S * DD];
__device__ __align__(256) float g_tT [BNT * S * DD];
__device__ __align__(256) float g_tnh[BNT * S * DD];   // tn hi; reused as hn
__device__ __align__(256) float g_tnl[BNT * S * DD];
__device__ __align__(256) float g_p  [(long)BNT * S * S];
__device__ __align__(256) float g_yh [BNT * S * DD];   // att, then y hi
__device__ __align__(256) float g_yl [BNT * S * DD];
__device__ __align__(256) float g_hf [BNT * S * FD];
__device__ __align__(256) float g_wih[DD * CD];
__device__ __align__(256) float g_wil[DD * CD];
__device__ __align__(256) float g_woh[CD * DD];
__device__ __align__(256) float g_wol[CD * DD];
__device__ __align__(256) float g_w1p[FD * DD];
__device__ __align__(256) float g_w2p[DD * FD];

// ---------------------------------------------------------------------------
__device__ __forceinline__ float tf32r(float x) {
    uint32_t u;
    asm("cvt.rna.tf32.f32 %0, %1;" : "=r"(u) : "f"(x));
    return __uint_as_float(u);
}

// k-permutation within 16-blocks (involution)
__device__ __forceinline__ int kperm(int k) {
    return (k & ~15) | ((k & 3) << 2) | ((k >> 2) & 3);
}

#define MMA_TF32(d, a0, a1, a2, a3, b0, b1)                                   \
    asm volatile("mma.sync.aligned.m16n8k8.row.col.f32.tf32.tf32.f32 "        \
                 "{%0,%1,%2,%3}, {%4,%5,%6,%7}, {%8,%9}, {%0,%1,%2,%3};\n"    \
                 : "+f"(d[0]), "+f"(d[1]), "+f"(d[2]), "+f"(d[3])             \
                 : "r"(a0), "r"(a1), "r"(a2), "r"(a3), "r"(b0), "r"(b1))

#define UF(x) __float_as_uint(x)

#define CP16(dst, src)                                                        \
    asm volatile("cp.async.cg.shared.global [%0], [%1], 16;\n"                \
                 :: "r"(dst), "l"(src))

__device__ __forceinline__ int sw_addr(int m, int q) {
    return m * 16 + (((q ^ ((m >> 1) & 3)) & 3) << 2);
}

// ---------------------------------------------------------------------------
// tf32 mma GEMM: cp.async 3-stage pipeline, k-permuted gmem operands.
// MODE  : 0 = BK32 single-pass (stage holds two BK16 k-halves; operands
//             pre-rounded rna in producers)
//         1 = BK16 3xTF32 (stage holds hi + lo)
// EPI   : 0 store, 1 relu+rna+perm-col, 2 +R store, 3 scatter to out,
//         4 +R, hi/lo split, perm-col
// CAUSAL: 1 tile skip (scores), 2 K limited to m0+128 (P@V)
// Stage layout (floats): [A0:0..2047][B0:2048..3071][A1:3072..5119][B1:5120..6143]
//   MODE 1: A0/B0 = hi, A1/B1 = lo (same k).  MODE 0: A1/B1 = k+16 half.
// ---------------------------------------------------------------------------
template<int MODE, int EPI, int CAUSAL>
__global__ __launch_bounds__(256, 2)
void mma_gemm(const float* __restrict__ A, const float* __restrict__ Al_,
              long sAbn, int lda,
              const float* __restrict__ B, const float* __restrict__ Bl_,
              long sBbn, int ldb,
              float* __restrict__ C, float* __restrict__ C2, long sCbn, int ldc,
              const float* __restrict__ R, long sRbn,
              float* __restrict__ Op, int K)
{
    const int bx = blockIdx.x, by = blockIdx.y, bz = blockIdx.z;
    if (CAUSAL == 1 && bx > 2 * by + 1) return;

    constexpr int SS = 6144;
    extern __shared__ __align__(16) float sh[];

    const int tid = threadIdx.x;
    const int w = tid >> 5, l = tid & 31;
    const int warp_m = (w & 3) * 32, warp_n = (w >> 2) * 32;
    const int g = l >> 2, cc = l & 3;
    const int m0 = by * 128, n0 = bx * 64;

    const float* Ab  = A + (long)bz * sAbn;
    const float* Bb  = B + (long)bz * sBbn;
    const float* Abl = (MODE == 1) ? (Al_ + (long)bz * sAbn) : nullptr;
    const float* Bbl = (MODE == 1) ? (Bl_ + (long)bz * sBbn) : nullptr;

    int Keff = K;
    if (CAUSAL == 2) { int lim = m0 + 128; if (lim < Keff) Keff = lim; }
    const int nk = (MODE == 0) ? (Keff >> 5) : (Keff >> 4);

    const int am = tid >> 2, aj = tid & 3;
    const long oA0 = (long)(m0 + am)      * lda + aj * 4;
    const long oA1 = (long)(m0 + am + 64) * lda + aj * 4;
    const long oB  = (long)(n0 + am)      * ldb + aj * 4;
    const int swz  = ((aj ^ ((am >> 1) & 3)) & 3) << 2;
    const int slA0 = am * 16 + swz;
    const int slA1 = (am + 64) * 16 + swz;
    const int slB  = 2048 + am * 16 + swz;
    const uint32_t sb = (uint32_t)__cvta_generic_to_shared(sh);

    auto issue = [&](int st, int kt) {
        uint32_t s0 = sb + (uint32_t)(st * SS) * 4u;
        if (MODE == 0) {
            long ko = (long)kt * 32;
            CP16(s0 + slA0 * 4, Ab + oA0 + ko);
            CP16(s0 + slA1 * 4, Ab + oA1 + ko);
            CP16(s0 + slB  * 4, Bb + oB  + ko);
            CP16(s0 + (slA0 + 3072) * 4, Ab + oA0 + ko + 16);
            CP16(s0 + (slA1 + 3072) * 4, Ab + oA1 + ko + 16);
            CP16(s0 + (slB  + 3072) * 4, Bb + oB  + ko + 16);
        } else {
            long ko = (long)kt * 16;
            CP16(s0 + slA0 * 4, Ab + oA0 + ko);
            CP16(s0 + slA1 * 4, Ab + oA1 + ko);
            CP16(s0 + slB  * 4, Bb + oB  + ko);
            CP16(s0 + (slA0 + 3072) * 4, Abl + oA0 + ko);
            CP16(s0 + (slA1 + 3072) * 4, Abl + oA1 + ko);
            CP16(s0 + (slB  + 3072) * 4, Bbl + oB  + ko);
        }
        asm volatile("cp.async.commit_group;\n" ::);
    };

    float acc[2][4][4] = {};

    issue(0, 0);
    if (nk > 1) issue(1, 1);
    else        asm volatile("cp.async.commit_group;\n" ::);

    for (int kt = 0; kt < nk; kt++) {
        asm volatile("cp.async.wait_group 1;\n" ::);
        __syncthreads();
        if (kt + 2 < nk) issue((kt + 2) % 3, kt + 2);
        else             asm volatile("cp.async.commit_group;\n" ::);

        const float* s0A = sh + (kt % 3) * SS;
        const float* s0B = s0A + 2048;
        const float* s1A = s0A + 3072;
        const float* s1B = s0A + 5120;

        float4 Ah[2][2], Bh[4], Al[2][2], Bl[4];
        #pragma unroll
        for (int mi = 0; mi < 2; mi++) {
            int mr = warp_m + mi * 16 + g;
            Ah[mi][0] = *(const float4*)&s0A[sw_addr(mr, cc)];
            Ah[mi][1] = *(const float4*)&s0A[sw_addr(mr + 8, cc)];
            Al[mi][0] = *(const float4*)&s1A[sw_addr(mr, cc)];
            Al[mi][1] = *(const float4*)&s1A[sw_addr(mr + 8, cc)];
        }
        #pragma unroll
        for (int nj = 0; nj < 4; nj++) {
            int nr = warp_n + nj * 8 + g;
            Bh[nj] = *(const float4*)&s0B[sw_addr(nr, cc)];
            Bl[nj] = *(const float4*)&s1B[sw_addr(nr, cc)];
        }

        #pragma unroll
        for (int mi = 0; mi < 2; mi++) {
            #pragma unroll
            for (int nj = 0; nj < 4; nj++) {
                float* d = acc[mi][nj];
                MMA_TF32(d, UF(Ah[mi][0].x), UF(Ah[mi][1].x), UF(Ah[mi][0].y), UF(Ah[mi][1].y),
                            UF(Bh[nj].x), UF(Bh[nj].y));
                if (MODE == 1) {
                    MMA_TF32(d, UF(Ah[mi][0].x), UF(Ah[mi][1].x), UF(Ah[mi][0].y), UF(Ah[mi][1].y),
                                UF(Bl[nj].x), UF(Bl[nj].y));
                    MMA_TF32(d, UF(Al[mi][0].x), UF(Al[mi][1].x), UF(Al[mi][0].y), UF(Al[mi][1].y),
                                UF(Bh[nj].x), UF(Bh[nj].y));
                }
                MMA_TF32(d, UF(Ah[mi][0].z), UF(Ah[mi][1].z), UF(Ah[mi][0].w), UF(Ah[mi][1].w),
                            UF(Bh[nj].z), UF(Bh[nj].w));
                if (MODE == 1) {
                    MMA_TF32(d, UF(Ah[mi][0].z), UF(Ah[mi][1].z), UF(Ah[mi][0].w), UF(Ah[mi][1].w),
                                UF(Bl[nj].z), UF(Bl[nj].w));
                    MMA_TF32(d, UF(Al[mi][0].z), UF(Al[mi][1].z), UF(Al[mi][0].w), UF(Al[mi][1].w),
                                UF(Bh[nj].z), UF(Bh[nj].w));
                }
                if (MODE == 0) {   // second k-half
                    MMA_TF32(d, UF(Al[mi][0].x), UF(Al[mi][1].x), UF(Al[mi][0].y), UF(Al[mi][1].y),
                                UF(Bl[nj].x), UF(Bl[nj].y));
                    MMA_TF32(d, UF(Al[mi][0].z), UF(Al[mi][1].z), UF(Al[mi][0].w), UF(Al[mi][1].w),
                                UF(Bl[nj].z), UF(Bl[nj].w));
                }
            }
        }
    }

    // ---- epilogue ----
    if (EPI == 3) {
        const int b = bz >> 3, n = bz & 7;
        #pragma unroll
        for (int mi = 0; mi < 2; mi++) {
            #pragma unroll
            for (int nj = 0; nj < 4; nj++) {
                int row = m0 + warp_m + mi * 16 + g;
                int col = n0 + warp_n + nj * 8 + 2 * cc;
                Op[((long)(b * 64 + col)     * 8 + n) * 1024 + row]     = acc[mi][nj][0];
                Op[((long)(b * 64 + col + 1) * 8 + n) * 1024 + row]     = acc[mi][nj][1];
                Op[((long)(b * 64 + col)     * 8 + n) * 1024 + row + 8] = acc[mi][nj][2];
                Op[((long)(b * 64 + col + 1) * 8 + n) * 1024 + row + 8] = acc[mi][nj][3];
            }
        }
    } else if (EPI == 1) {
        float* Cb = C + (long)bz * sCbn;
        #pragma unroll
        for (int mi = 0; mi < 2; mi++) {
            #pragma unroll
            for (int nj = 0; nj < 4; nj++) {
                int row = m0 + warp_m + mi * 16 + g;
                int col = n0 + warp_n + nj * 8 + 2 * cc;
                int p0 = kperm(col), p1 = kperm(col + 1);
                Cb[(long)row * ldc + p0]       = tf32r(fmaxf(acc[mi][nj][0], 0.f));
                Cb[(long)row * ldc + p1]       = tf32r(fmaxf(acc[mi][nj][1], 0.f));
                Cb[(long)(row + 8) * ldc + p0] = tf32r(fmaxf(acc[mi][nj][2], 0.f));
                Cb[(long)(row + 8) * ldc + p1] = tf32r(fmaxf(acc[mi][nj][3], 0.f));
            }
        }
    } else if (EPI == 4) {
        float* Cb  = C  + (long)bz * sCbn;
        float* C2b = C2 + (long)bz * sCbn;
        const float* Rb = R + (long)bz * sRbn;
        #pragma unroll
        for (int mi = 0; mi < 2; mi++) {
            #pragma unroll
            for (int nj = 0; nj < 4; nj++) {
                int row = m0 + warp_m + mi * 16 + g;
                int col = n0 + warp_n + nj * 8 + 2 * cc;
                int p0 = kperm(col), p1 = kperm(col + 1);
                float2 r0 = *(const float2*)(Rb + (long)row * ldc + col);
                float2 r1 = *(const float2*)(Rb + (long)(row + 8) * ldc + col);
                float v[4] = {acc[mi][nj][0] + r0.x, acc[mi][nj][1] + r0.y,
                              acc[mi][nj][2] + r1.x, acc[mi][nj][3] + r1.y};
                float h[4], lo[4];
                #pragma unroll
                for (int q = 0; q < 4; q++) { h[q] = tf32r(v[q]); lo[q] = tf32r(v[q] - h[q]); }
                Cb [(long)row * ldc + p0]       = h[0];
                Cb [(long)row * ldc + p1]       = h[1];
                Cb [(long)(row + 8) * ldc + p0] = h[2];
                Cb [(long)(row + 8) * ldc + p1] = h[3];
                C2b[(long)row * ldc + p0]       = lo[0];
                C2b[(long)row * ldc + p1]       = lo[1];
                C2b[(long)(row + 8) * ldc + p0] = lo[2];
                C2b[(long)(row + 8) * ldc + p1] = lo[3];
            }
        }
    } else {
        float* Cb = C + (long)bz * sCbn;
        const float* Rb = (EPI == 2) ? (R + (long)bz * sRbn) : nullptr;
        #pragma unroll
        for (int mi = 0; mi < 2; mi++) {
            #pragma unroll
            for (int nj = 0; nj < 4; nj++) {
                int row = m0 + warp_m + mi * 16 + g;
                int col = n0 + warp_n + nj * 8 + 2 * cc;
                float v[4] = {acc[mi][nj][0], acc[mi][nj][1], acc[mi][nj][2], acc[mi][nj][3]};
                if (EPI == 2) {
                    float2 r0 = *(const float2*)(Rb + (long)row * ldc + col);
                    float2 r1 = *(const float2*)(Rb + (long)(row + 8) * ldc + col);
                    v[0] += r0.x; v[1] += r0.y; v[2] += r1.x; v[3] += r1.y;
                }
                *(float2*)(Cb + (long)row * ldc + col)       = make_float2(v[0], v[1]);
                *(float2*)(Cb + (long)(row + 8) * ldc + col) = make_float2(v[2], v[3]);
            }
        }
    }
}

// ---------------------------------------------------------------------------
// One kernel for all weight prep: W_in hi/lo, W_out hi/lo, W1 rna, W2 rna.
// ---------------------------------------------------------------------------
__global__ __launch_bounds__(256)
void wprep_k(const float* __restrict__ W_in, const float* __restrict__ W_out,
             const float* __restrict__ W1, const float* __restrict__ W2,
             float* __restrict__ wih, float* __restrict__ wil,
             float* __restrict__ woh, float* __restrict__ wol,
             float* __restrict__ w1p, float* __restrict__ w2p)
{
    int i = blockIdx.x * 256 + threadIdx.x;
    const int nWi = DD * CD, nWo = CD * DD, nW1 = FD * DD;
    if (i < nWi) {
        int row = i / CD, k = i % CD;
        float v = W_in[i], h = tf32r(v);
        int o = row * CD + kperm(k);
        wih[o] = h; wil[o] = tf32r(v - h);
    } else if (i < nWi + nWo) {
        int j = i - nWi;
        int row = j / DD, k = j % DD;
        float v = W_out[j], h = tf32r(v);
        int o = row * DD + kperm(k);
        woh[o] = h; wol[o] = tf32r(v - h);
    } else if (i < nWi + nWo + nW1) {
        int j = i - nWi - nWo;
        int row = j / DD, k = j % DD;
        w1p[row * DD + kperm(k)] = tf32r(W1[j]);
    } else {
        int j = i - nWi - nWo - nW1;
        if (j < DD * FD) {
            int row = j / FD, k = j % FD;
            w2p[row * FD + kperm(k)] = tf32r(W2[j]);
        }
    }
}

__global__ __launch_bounds__(256)
void transpose_x_k(const float* __restrict__ x, float* __restrict__ xth,
                   float* __restrict__ xtl)
{
    __shared__ float tile[32][33];
    int tx = threadIdx.x & 31, ty = threadIdx.x >> 5;
    int bn = blockIdx.z, b = bn >> 3, n = bn & 7;
    int s0 = blockIdx.x * 32, c0 = blockIdx.y * 32;
    const float* src = x + ((long)b * 64 * 8 + n) * 1024;
    #pragma unroll
    for (int i = 0; i < 4; i++)
        tile[ty + 8 * i][tx] = src[(long)(c0 + ty + 8 * i) * 8192 + s0 + tx];
    __syncthreads();
    float* dh = xth + (long)bn * (S * CD);
    float* dl = xtl + (long)bn * (S * CD);
    int pc = kperm(c0 + tx);
    #pragma unroll
    for (int i = 0; i < 4; i++) {
        float v = tile[tx][ty + 8 * i];
        float h = tf32r(v);
        long idx = (long)(s0 + ty + 8 * i) * 64 + pc;
        dh[idx] = h;
        dl[idx] = tf32r(v - h);
    }
}

__global__ __launch_bounds__(256)
void transpose_t_k(const float* __restrict__ t, float* __restrict__ tT)
{
    __shared__ float tile[32][33];
    int tx = threadIdx.x & 31, ty = threadIdx.x >> 5;
    int bn = blockIdx.z;
    int s0 = blockIdx.x * 32, d0 = blockIdx.y * 32;
    const float* src = t + (long)bn * (S * DD);
    #pragma unroll
    for (int i = 0; i < 4; i++)
        tile[ty + 8 * i][tx] = src[(long)(s0 + ty + 8 * i) * 256 + d0 + tx];
    __syncthreads();
    float* dst = tT + (long)bn * (S * DD);
    int ps = kperm(s0 + tx);
    #pragma unroll
    for (int i = 0; i < 4; i++)
        dst[(long)(d0 + ty + 8 * i) * 1024 + ps] = tf32r(tile[tx][ty + 8 * i]);
}

// ---------------------------------------------------------------------------
// WRITE_SPLIT 1: hi/lo (perm). 0: single rna-rounded (perm) — feeds FFN1.
// ---------------------------------------------------------------------------
template<int WRITE_SPLIT>
__global__ __launch_bounds__(256)
void ln_k(const float* __restrict__ in, float* __restrict__ out,
          float* __restrict__ out_lo,
          const float* __restrict__ gam, const float* __restrict__ bet)
{
    int warp = (blockIdx.x * blockDim.x + threadIdx.x) >> 5;
    int lane = threadIdx.x & 31;
    const float* x = in + (long)warp * DD;

    float v[8], s = 0.f, ss = 0.f;
    #pragma unroll
    for (int i = 0; i < 8; i++) {
        v[i] = x[lane + 32 * i];
        s += v[i]; ss += v[i] * v[i];
    }
    #pragma unroll
    for (int o = 16; o; o >>= 1) {
        s  += __shfl_xor_sync(0xffffffffu, s,  o);
        ss += __shfl_xor_sync(0xffffffffu, ss, o);
    }
    float mu = s * (1.f / DD);
    float var = ss * (1.f / DD) - mu * mu;
    float rs = rsqrtf(var + 1e-5f);

    float* o_ = out + (long)warp * DD;
    float* ol = WRITE_SPLIT ? (out_lo + (long)warp * DD) : nullptr;
    #pragma unroll
    for (int i = 0; i < 8; i++) {
        int c = lane + 32 * i;
        int pc = kperm(c);
        float y = (v[i] - mu) * rs * gam[c] + bet[c];
        if (WRITE_SPLIT) {
            float h = tf32r(y);
            o_[pc] = h;
            ol[pc] = tf32r(y - h);
        } else {
            o_[pc] = tf32r(y);
        }
    }
}

// ---------------------------------------------------------------------------
__global__ __launch_bounds__(256)
void softmax_k(float* __restrict__ p)
{
    int warp = (blockIdx.x * blockDim.x + threadIdx.x) >> 5;
    int lane = threadIdx.x & 31;
    int q = warp & (S - 1);
    float* row = p + (long)warp * S;

    float v[32], mx = -3.4e38f;
    #pragma unroll
    for (int i = 0; i < 32; i++) {
        int col = lane + 32 * i;
        v[i] = (col <= q) ? row[col] : -3.4e38f;
        mx = fmaxf(mx, v[i]);
    }
    #pragma unroll
    for (int o = 16; o; o >>= 1) mx = fmaxf(mx, __shfl_xor_sync(0xffffffffu, mx, o));

    float sum = 0.f;
    #pragma unroll
    for (int i = 0; i < 32; i++) {
        int col = lane + 32 * i;
        v[i] = (col <= q) ? expf(v[i] - mx) : 0.f;
        sum += v[i];
    }
    #pragma unroll
    for (int o = 16; o; o >>= 1) sum += __shfl_xor_sync(0xffffffffu, sum, o);
    float inv = 1.f / sum;

    int kend = ((q >> 7) + 1) << 7;
    #pragma unroll
    for (int i = 0; i < 32; i++) {
        int col = lane + 32 * i;
        if (col < kend) row[kperm(col)] = tf32r(v[i] * inv);
    }
}

// ---------------------------------------------------------------------------
extern "C" void kernel_launch(void* const* d_in, const int* in_sizes, int n_in,
                              void* d_out, int out_size)
{
    (void)in_sizes; (void)n_in; (void)out_size;
    const float* buffer = (const float*)d_in[0];
    const float* W_in   = (const float*)d_in[1];
    const float* ln1_g  = (const float*)d_in[2];
    const float* ln1_b  = (const float*)d_in[3];
    const float* ln2_g  = (const float*)d_in[4];
    const float* ln2_b  = (const float*)d_in[5];
    const float* W1     = (const float*)d_in[6];
    const float* W2     = (const float*)d_in[7];
    const float* W_out  = (const float*)d_in[8];
    float* out = (float*)d_out;

    float *xth, *xtl, *t, *tT, *tnh, *tnl, *p, *yh, *yl, *hf;
    float *wih, *wil, *woh, *wol, *w1p, *w2p;
    cudaGetSymbolAddress((void**)&xth, g_xth);
    cudaGetSymbolAddress((void**)&xtl, g_xtl);
    cudaGetSymbolAddress((void**)&t,   g_t);
    cudaGetSymbolAddress((void**)&tT,  g_tT);
    cudaGetSymbolAddress((void**)&tnh, g_tnh);
    cudaGetSymbolAddress((void**)&tnl, g_tnl);
    cudaGetSymbolAddress((void**)&p,   g_p);
    cudaGetSymbolAddress((void**)&yh,  g_yh);
    cudaGetSymbolAddress((void**)&yl,  g_yl);
    cudaGetSymbolAddress((void**)&hf,  g_hf);
    cudaGetSymbolAddress((void**)&wih, g_wih);
    cudaGetSymbolAddress((void**)&wil, g_wil);
    cudaGetSymbolAddress((void**)&woh, g_woh);
    cudaGetSymbolAddress((void**)&wol, g_wol);
    cudaGetSymbolAddress((void**)&w1p, g_w1p);
    cudaGetSymbolAddress((void**)&w2p, g_w2p);

    const long sT = (long)S * DD;
    const long sP = (long)S * S;
    const long sH = (long)S * FD;
    const long sX = (long)S * CD;

    const int smem_b = 3 * 6144 * 4;   // 73728 B, all modes
    cudaFuncSetAttribute(mma_gemm<1, 0, 0>, cudaFuncAttributeMaxDynamicSharedMemorySize, smem_b);
    cudaFuncSetAttribute(mma_gemm<1, 0, 1>, cudaFuncAttributeMaxDynamicSharedMemorySize, smem_b);
    cudaFuncSetAttribute(mma_gemm<1, 3, 0>, cudaFuncAttributeMaxDynamicSharedMemorySize, smem_b);
    cudaFuncSetAttribute(mma_gemm<0, 2, 2>, cudaFuncAttributeMaxDynamicSharedMemorySize, smem_b);
    cudaFuncSetAttribute(mma_gemm<0, 1, 0>, cudaFuncAttributeMaxDynamicSharedMemorySize, smem_b);
    cudaFuncSetAttribute(mma_gemm<0, 4, 0>, cudaFuncAttributeMaxDynamicSharedMemorySize, smem_b);

    // weight prep (single kernel)
    {
        const int ntot = DD * CD + CD * DD + FD * DD + DD * FD;
        wprep_k<<<(ntot + 255) / 256, 256>>>(W_in, W_out, W1, W2,
                                             wih, wil, woh, wol, w1p, w2p);
    }

    // 0) transpose x -> xt hi/lo (c-permuted)
    transpose_x_k<<<dim3(32, 2, BNT), 256>>>(buffer, xth, xtl);

    // 1) t = xt . W_in^T   (split)
    mma_gemm<1, 0, 0><<<dim3(4, 8, BNT), 256, smem_b>>>(
        xth, xtl, sX, CD,  wih, wil, 0, CD,
        t, nullptr, sT, DD,  nullptr, 0, nullptr, CD);

    // 2) tn = LN1(t), hi/lo (d-permuted)
    ln_k<1><<<(BNT * S) / 8, 256>>>(t, tnh, tnl, ln1_g, ln1_b);

    // 3) scores = tn . tn^T  (split, causal tile skip)
    mma_gemm<1, 0, 1><<<dim3(16, 8, BNT), 256, smem_b>>>(
        tnh, tnl, sT, DD,  tnh, tnl, sT, DD,
        p, nullptr, sP, S,  nullptr, 0, nullptr, DD);

    // 4) softmax (rna-rounded, k-permuted p)
    softmax_k<<<(BNT * S) / 8, 256>>>(p);

    // 5) transpose t -> tT (s-permuted, rna-rounded)
    transpose_t_k<<<dim3(32, 8, BNT), 256>>>(t, tT);

    // 6) att = p . t + t    (BK32 single, K limited)
    mma_gemm<0, 2, 2><<<dim3(4, 8, BNT), 256, smem_b>>>(
        p, nullptr, sP, S,  tT, nullptr, sT, S,
        yh, nullptr, sT, DD,  t, sT, nullptr, S);

    // 7) hn = LN2(att) -> tnh (rna-rounded, d-permuted)
    ln_k<0><<<(BNT * S) / 8, 256>>>(yh, tnh, nullptr, ln2_g, ln2_b);

    // 8) hf = relu(hn . W1^T)  (BK32, rna+f-permuted output)
    mma_gemm<0, 1, 0><<<dim3(8, 8, BNT), 256, smem_b>>>(
        tnh, nullptr, sT, DD,  w1p, nullptr, 0, DD,
        hf, nullptr, sH, FD,  nullptr, 0, nullptr, DD);

    // 9) y = hf . W2^T + t  -> yh/yl (BK32, split d-permuted output)
    mma_gemm<0, 4, 0><<<dim3(4, 8, BNT), 256, smem_b>>>(
        hf, nullptr, sH, FD,  w2p, nullptr, 0, FD,
        yh, yl, sT, DD,  t, sT, nullptr, FD);

    // 10) out = y . W_out^T (split, scatter epilogue)
    mma_gemm<1, 3, 0><<<dim3(1, 8, BNT), 256, smem_b>>>(
        yh, yl, sT, DD,  woh, wol, 0, DD,
        nullptr, nullptr, 0, 0,  nullptr, 0, out, DD);
}

// round 7
// speedup vs baseline: 1.6675x; 1.2366x over previous
#include <cuda_runtime.h>
#include <cuda_bf16.h>
#include <cstdint>

#define S    1024
#define CD   64
#define DD   256
#define FD   512
#define BNT  32

// bf16 buffers (split operands)
__device__ __align__(256) __nv_bfloat16 g_xth[BNT * S * CD];
__device__ __align__(256) __nv_bfloat16 g_xtl[BNT * S * CD];
__device__ __align__(256) __nv_bfloat16 g_tnh[BNT * S * DD];
__device__ __align__(256) __nv_bfloat16 g_tnl[BNT * S * DD];
__device__ __align__(256) __nv_bfloat16 g_ybh[BNT * S * DD];
__device__ __align__(256) __nv_bfloat16 g_ybl[BNT * S * DD];
__device__ __align__(256) __nv_bfloat16 g_wih[DD * CD];
__device__ __align__(256) __nv_bfloat16 g_wil[DD * CD];
__device__ __align__(256) __nv_bfloat16 g_woh[CD * DD];
__device__ __align__(256) __nv_bfloat16 g_wol[CD * DD];
// fp32 buffers
__device__ __align__(256) float g_t  [BNT * S * DD];
__device__ __align__(256) float g_tT [BNT * S * DD];
__device__ __align__(256) float g_hn [BNT * S * DD];
__device__ __align__(256) float g_p  [(long)BNT * S * S];
__device__ __align__(256) float g_att[BNT * S * DD];
__device__ __align__(256) float g_hf [BNT * S * FD];
__device__ __align__(256) float g_w1p[FD * DD];
__device__ __align__(256) float g_w2p[DD * FD];

// ---------------------------------------------------------------------------
__device__ __forceinline__ float tf32r(float x) {
    uint32_t u;
    asm("cvt.rna.tf32.f32 %0, %1;" : "=r"(u) : "f"(x));
    return __uint_as_float(u);
}

// tf32 k-perm within 16 (MODE 0 operands)
__device__ __forceinline__ int kperm(int k) {
    return (k & ~15) | ((k & 3) << 2) | ((k >> 2) & 3);
}
// bf16 k-perm within 32 (MODE 1 operands): chunk=(k>>1)&3, pos=((k>>3)&3)*2+(k&1)
__device__ __forceinline__ int bperm(int k) {
    return (k & ~31) | (((k >> 1) & 3) << 3) | (((k >> 3) & 3) << 1) | (k & 1);
}

#define MMA_TF32(d, a0, a1, a2, a3, b0, b1)                                   \
    asm volatile("mma.sync.aligned.m16n8k8.row.col.f32.tf32.tf32.f32 "        \
                 "{%0,%1,%2,%3}, {%4,%5,%6,%7}, {%8,%9}, {%0,%1,%2,%3};\n"    \
                 : "+f"(d[0]), "+f"(d[1]), "+f"(d[2]), "+f"(d[3])             \
                 : "r"(a0), "r"(a1), "r"(a2), "r"(a3), "r"(b0), "r"(b1))

#define MMA_BF16(d, a0, a1, a2, a3, b0, b1)                                   \
    asm volatile("mma.sync.aligned.m16n8k16.row.col.f32.bf16.bf16.f32 "       \
                 "{%0,%1,%2,%3}, {%4,%5,%6,%7}, {%8,%9}, {%0,%1,%2,%3};\n"    \
                 : "+f"(d[0]), "+f"(d[1]), "+f"(d[2]), "+f"(d[3])             \
                 : "r"(a0), "r"(a1), "r"(a2), "r"(a3), "r"(b0), "r"(b1))

#define UF(x) __float_as_uint(x)

#define CP16(dst, src)                                                        \
    asm volatile("cp.async.cg.shared.global [%0], [%1], 16;\n"                \
                 :: "r"(dst), "l"(src))

__device__ __forceinline__ int sw_addr(int m, int q) {
    return m * 16 + (((q ^ ((m >> 1) & 3)) & 3) << 2);
}

__device__ __forceinline__ void bf16split(float v, __nv_bfloat16& h, __nv_bfloat16& l) {
    h = __float2bfloat16_rn(v);
    l = __float2bfloat16_rn(v - __bfloat162float(h));
}

// ---------------------------------------------------------------------------
// cp.async 3-stage pipelined MMA GEMM, BK=32 for both modes.
// MODE 0: fp32 operands (pre-rounded rna-tf32, kperm), tf32 k8 MMAs.
// MODE 1: bf16 hi/lo operands (bperm), 2-term-split bf16 k16 MMAs (hh+hl+lh).
// EPI  : 0 store, 1 relu+rna+kperm-col, 2 +R store, 3 scatter to out layout,
//        4 +R then bf16 hi/lo split, bperm-col
// CAUSAL: 1 tile skip (scores), 2 K limited to m0+128 (P@V)
// Stage = 6144 words: [A0:0..2047][B0:2048..3071][A1:3072..5119][B1:5120..6143]
//   MODE 0: A1/B1 = second k16 half.  MODE 1: A1/B1 = lo parts (full k32).
// ---------------------------------------------------------------------------
template<int MODE, int EPI, int CAUSAL>
__global__ __launch_bounds__(256, 2)
void mma_gemm(const void* __restrict__ A, const void* __restrict__ Al_,
              long sAbn, int lda,
              const void* __restrict__ B, const void* __restrict__ Bl_,
              long sBbn, int ldb,
              float* __restrict__ C, float* __restrict__ C2, long sCbn, int ldc,
              const float* __restrict__ R, long sRbn,
              float* __restrict__ Op, int K)
{
    const int bx = blockIdx.x, by = blockIdx.y, bz = blockIdx.z;
    if (CAUSAL == 1 && bx > 2 * by + 1) return;

    constexpr int SS  = 6144;                    // words per stage
    constexpr int ESZ = (MODE == 1) ? 2 : 4;     // element bytes
    constexpr int CE  = 16 / ESZ;                // elems per 16B chunk
    extern __shared__ __align__(16) float sh[];

    const int tid = threadIdx.x;
    const int w = tid >> 5, l = tid & 31;
    const int warp_m = (w & 3) * 32, warp_n = (w >> 2) * 32;
    const int g = l >> 2, cc = l & 3;
    const int m0 = by * 128, n0 = bx * 64;

    const char* Abp  = (const char*)A + (long)bz * sAbn * ESZ;
    const char* Bbp  = (const char*)B + (long)bz * sBbn * ESZ;
    const char* Ablp = (MODE == 1) ? ((const char*)Al_ + (long)bz * sAbn * ESZ) : nullptr;
    const char* Bblp = (MODE == 1) ? ((const char*)Bl_ + (long)bz * sBbn * ESZ) : nullptr;

    int Keff = K;
    if (CAUSAL == 2) { int lim = m0 + 128; if (lim < Keff) Keff = lim; }
    const int nk = Keff >> 5;

    const int am = tid >> 2, aj = tid & 3;
    const long oA0 = ((long)(m0 + am)      * lda + (long)aj * CE) * ESZ;  // bytes
    const long oA1 = ((long)(m0 + am + 64) * lda + (long)aj * CE) * ESZ;
    const long oB  = ((long)(n0 + am)      * ldb + (long)aj * CE) * ESZ;
    const int swz  = ((aj ^ ((am >> 1) & 3)) & 3) << 2;
    const int slA0 = am * 16 + swz;
    const int slA1 = (am + 64) * 16 + swz;
    const int slB  = 2048 + am * 16 + swz;
    const uint32_t sb = (uint32_t)__cvta_generic_to_shared(sh);

    auto issue = [&](int st, int kt) {
        uint32_t s0 = sb + (uint32_t)(st * SS) * 4u;
        long kb = (long)kt * 32 * ESZ;
        if (MODE == 0) {
            CP16(s0 + slA0 * 4, Abp + oA0 + kb);
            CP16(s0 + slA1 * 4, Abp + oA1 + kb);
            CP16(s0 + slB  * 4, Bbp + oB  + kb);
            CP16(s0 + (slA0 + 3072) * 4, Abp + oA0 + kb + 64);
            CP16(s0 + (slA1 + 3072) * 4, Abp + oA1 + kb + 64);
            CP16(s0 + (slB  + 3072) * 4, Bbp + oB  + kb + 64);
        } else {
            CP16(s0 + slA0 * 4, Abp + oA0 + kb);
            CP16(s0 + slA1 * 4, Abp + oA1 + kb);
            CP16(s0 + slB  * 4, Bbp + oB  + kb);
            CP16(s0 + (slA0 + 3072) * 4, Ablp + oA0 + kb);
            CP16(s0 + (slA1 + 3072) * 4, Ablp + oA1 + kb);
            CP16(s0 + (slB  + 3072) * 4, Bblp + oB  + kb);
        }
        asm volatile("cp.async.commit_group;\n" ::);
    };

    float acc[2][4][4] = {};

    issue(0, 0);
    if (nk > 1) issue(1, 1);
    else        asm volatile("cp.async.commit_group;\n" ::);

    for (int kt = 0; kt < nk; kt++) {
        asm volatile("cp.async.wait_group 1;\n" ::);
        __syncthreads();
        if (kt + 2 < nk) issue((kt + 2) % 3, kt + 2);
        else             asm volatile("cp.async.commit_group;\n" ::);

        const float* s0A = sh + (kt % 3) * SS;
        const float* s0B = s0A + 2048;
        const float* s1A = s0A + 3072;
        const float* s1B = s0A + 5120;

        float4 Ah[2][2], Bh[4], Al[2][2], Bl[4];
        #pragma unroll
        for (int mi = 0; mi < 2; mi++) {
            int mr = warp_m + mi * 16 + g;
            Ah[mi][0] = *(const float4*)&s0A[sw_addr(mr, cc)];
            Ah[mi][1] = *(const float4*)&s0A[sw_addr(mr + 8, cc)];
            Al[mi][0] = *(const float4*)&s1A[sw_addr(mr, cc)];
            Al[mi][1] = *(const float4*)&s1A[sw_addr(mr + 8, cc)];
        }
        #pragma unroll
        for (int nj = 0; nj < 4; nj++) {
            int nr = warp_n + nj * 8 + g;
            Bh[nj] = *(const float4*)&s0B[sw_addr(nr, cc)];
            Bl[nj] = *(const float4*)&s1B[sw_addr(nr, cc)];
        }

        #pragma unroll
        for (int mi = 0; mi < 2; mi++) {
            #pragma unroll
            for (int nj = 0; nj < 4; nj++) {
                float* d = acc[mi][nj];
                if (MODE == 0) {
                    // k8 x4 over the two k16 halves (single tf32)
                    MMA_TF32(d, UF(Ah[mi][0].x), UF(Ah[mi][1].x), UF(Ah[mi][0].y), UF(Ah[mi][1].y),
                                UF(Bh[nj].x), UF(Bh[nj].y));
                    MMA_TF32(d, UF(Ah[mi][0].z), UF(Ah[mi][1].z), UF(Ah[mi][0].w), UF(Ah[mi][1].w),
                                UF(Bh[nj].z), UF(Bh[nj].w));
                    MMA_TF32(d, UF(Al[mi][0].x), UF(Al[mi][1].x), UF(Al[mi][0].y), UF(Al[mi][1].y),
                                UF(Bl[nj].x), UF(Bl[nj].y));
                    MMA_TF32(d, UF(Al[mi][0].z), UF(Al[mi][1].z), UF(Al[mi][0].w), UF(Al[mi][1].w),
                                UF(Bl[nj].z), UF(Bl[nj].w));
                } else {
                    // bf16 2-term split: hh + h*lo + lo*h, two k16 halves
                    MMA_BF16(d, UF(Ah[mi][0].x), UF(Ah[mi][1].x), UF(Ah[mi][0].y), UF(Ah[mi][1].y),
                                UF(Bh[nj].x), UF(Bh[nj].y));
                    MMA_BF16(d, UF(Ah[mi][0].x), UF(Ah[mi][1].x), UF(Ah[mi][0].y), UF(Ah[mi][1].y),
                                UF(Bl[nj].x), UF(Bl[nj].y));
                    MMA_BF16(d, UF(Al[mi][0].x), UF(Al[mi][1].x), UF(Al[mi][0].y), UF(Al[mi][1].y),
                                UF(Bh[nj].x), UF(Bh[nj].y));
                    MMA_BF16(d, UF(Ah[mi][0].z), UF(Ah[mi][1].z), UF(Ah[mi][0].w), UF(Ah[mi][1].w),
                                UF(Bh[nj].z), UF(Bh[nj].w));
                    MMA_BF16(d, UF(Ah[mi][0].z), UF(Ah[mi][1].z), UF(Ah[mi][0].w), UF(Ah[mi][1].w),
                                UF(Bl[nj].z), UF(Bl[nj].w));
                    MMA_BF16(d, UF(Al[mi][0].z), UF(Al[mi][1].z), UF(Al[mi][0].w), UF(Al[mi][1].w),
                                UF(Bh[nj].z), UF(Bh[nj].w));
                }
            }
        }
    }

    // ---- epilogue ----
    if (EPI == 3) {
        const int b = bz >> 3, n = bz & 7;
        #pragma unroll
        for (int mi = 0; mi < 2; mi++) {
            #pragma unroll
            for (int nj = 0; nj < 4; nj++) {
                int row = m0 + warp_m + mi * 16 + g;
                int col = n0 + warp_n + nj * 8 + 2 * cc;
                Op[((long)(b * 64 + col)     * 8 + n) * 1024 + row]     = acc[mi][nj][0];
                Op[((long)(b * 64 + col + 1) * 8 + n) * 1024 + row]     = acc[mi][nj][1];
                Op[((long)(b * 64 + col)     * 8 + n) * 1024 + row + 8] = acc[mi][nj][2];
                Op[((long)(b * 64 + col + 1) * 8 + n) * 1024 + row + 8] = acc[mi][nj][3];
            }
        }
    } else if (EPI == 1) {
        float* Cb = C + (long)bz * sCbn;
        #pragma unroll
        for (int mi = 0; mi < 2; mi++) {
            #pragma unroll
            for (int nj = 0; nj < 4; nj++) {
                int row = m0 + warp_m + mi * 16 + g;
                int col = n0 + warp_n + nj * 8 + 2 * cc;
                int p0 = kperm(col), p1 = kperm(col + 1);
                Cb[(long)row * ldc + p0]       = tf32r(fmaxf(acc[mi][nj][0], 0.f));
                Cb[(long)row * ldc + p1]       = tf32r(fmaxf(acc[mi][nj][1], 0.f));
                Cb[(long)(row + 8) * ldc + p0] = tf32r(fmaxf(acc[mi][nj][2], 0.f));
                Cb[(long)(row + 8) * ldc + p1] = tf32r(fmaxf(acc[mi][nj][3], 0.f));
            }
        }
    } else if (EPI == 4) {
        __nv_bfloat16* Cb  = (__nv_bfloat16*)C  + (long)bz * sCbn;
        __nv_bfloat16* C2b = (__nv_bfloat16*)C2 + (long)bz * sCbn;
        const float* Rb = R + (long)bz * sRbn;
        #pragma unroll
        for (int mi = 0; mi < 2; mi++) {
            #pragma unroll
            for (int nj = 0; nj < 4; nj++) {
                int row = m0 + warp_m + mi * 16 + g;
                int col = n0 + warp_n + nj * 8 + 2 * cc;
                int p0 = bperm(col);            // bperm(col+1) == p0+1 (col even)
                float2 r0 = *(const float2*)(Rb + (long)row * ldc + col);
                float2 r1 = *(const float2*)(Rb + (long)(row + 8) * ldc + col);
                float v[4] = {acc[mi][nj][0] + r0.x, acc[mi][nj][1] + r0.y,
                              acc[mi][nj][2] + r1.x, acc[mi][nj][3] + r1.y};
                __nv_bfloat16 h[4], lo[4];
                #pragma unroll
                for (int q = 0; q < 4; q++) bf16split(v[q], h[q], lo[q]);
                *(__nv_bfloat162*)&Cb [(long)row * ldc + p0]       = __nv_bfloat162(h[0],  h[1]);
                *(__nv_bfloat162*)&Cb [(long)(row + 8) * ldc + p0] = __nv_bfloat162(h[2],  h[3]);
                *(__nv_bfloat162*)&C2b[(long)row * ldc + p0]       = __nv_bfloat162(lo[0], lo[1]);
                *(__nv_bfloat162*)&C2b[(long)(row + 8) * ldc + p0] = __nv_bfloat162(lo[2], lo[3]);
            }
        }
    } else {
        float* Cb = C + (long)bz * sCbn;
        const float* Rb = (EPI == 2) ? (R + (long)bz * sRbn) : nullptr;
        #pragma unroll
        for (int mi = 0; mi < 2; mi++) {
            #pragma unroll
            for (int nj = 0; nj < 4; nj++) {
                int row = m0 + warp_m + mi * 16 + g;
                int col = n0 + warp_n + nj * 8 + 2 * cc;
                float v[4] = {acc[mi][nj][0], acc[mi][nj][1], acc[mi][nj][2], acc[mi][nj][3]};
                if (EPI == 2) {
                    float2 r0 = *(const float2*)(Rb + (long)row * ldc + col);
                    float2 r1 = *(const float2*)(Rb + (long)(row + 8) * ldc + col);
                    v[0] += r0.x; v[1] += r0.y; v[2] += r1.x; v[3] += r1.y;
                }
                *(float2*)(Cb + (long)row * ldc + col)       = make_float2(v[0], v[1]);
                *(float2*)(Cb + (long)(row + 8) * ldc + col) = make_float2(v[2], v[3]);
            }
        }
    }
}

// ---------------------------------------------------------------------------
// Weight prep: W_in/W_out -> bf16 hi/lo (bperm); W1/W2 -> tf32-rounded (kperm)
// ---------------------------------------------------------------------------
__global__ __launch_bounds__(256)
void wprep_k(const float* __restrict__ W_in, const float* __restrict__ W_out,
             const float* __restrict__ W1, const float* __restrict__ W2,
             __nv_bfloat16* __restrict__ wih, __nv_bfloat16* __restrict__ wil,
             __nv_bfloat16* __restrict__ woh, __nv_bfloat16* __restrict__ wol,
             float* __restrict__ w1p, float* __restrict__ w2p)
{
    int i = blockIdx.x * 256 + threadIdx.x;
    const int nWi = DD * CD, nWo = CD * DD, nW1 = FD * DD;
    if (i < nWi) {
        int row = i / CD, k = i % CD;
        int o = row * CD + bperm(k);
        bf16split(W_in[i], wih[o], wil[o]);
    } else if (i < nWi + nWo) {
        int j = i - nWi;
        int row = j / DD, k = j % DD;
        int o = row * DD + bperm(k);
        bf16split(W_out[j], woh[o], wol[o]);
    } else if (i < nWi + nWo + nW1) {
        int j = i - nWi - nWo;
        int row = j / DD, k = j % DD;
        w1p[row * DD + kperm(k)] = tf32r(W1[j]);
    } else {
        int j = i - nWi - nWo - nW1;
        if (j < DD * FD) {
            int row = j / FD, k = j % FD;
            w2p[row * FD + kperm(k)] = tf32r(W2[j]);
        }
    }
}

__global__ __launch_bounds__(256)
void transpose_x_k(const float* __restrict__ x, __nv_bfloat16* __restrict__ xth,
                   __nv_bfloat16* __restrict__ xtl)
{
    __shared__ float tile[32][33];
    int tx = threadIdx.x & 31, ty = threadIdx.x >> 5;
    int bn = blockIdx.z, b = bn >> 3, n = bn & 7;
    int s0 = blockIdx.x * 32, c0 = blockIdx.y * 32;
    const float* src = x + ((long)b * 64 * 8 + n) * 1024;
    #pragma unroll
    for (int i = 0; i < 4; i++)
        tile[ty + 8 * i][tx] = src[(long)(c0 + ty + 8 * i) * 8192 + s0 + tx];
    __syncthreads();
    __nv_bfloat16* dh = xth + (long)bn * (S * CD);
    __nv_bfloat16* dl = xtl + (long)bn * (S * CD);
    int pc = bperm(c0 + tx);
    #pragma unroll
    for (int i = 0; i < 4; i++) {
        long idx = (long)(s0 + ty + 8 * i) * 64 + pc;
        bf16split(tile[tx][ty + 8 * i], dh[idx], dl[idx]);
    }
}

__global__ __launch_bounds__(256)
void transpose_t_k(const float* __restrict__ t, float* __restrict__ tT)
{
    __shared__ float tile[32][33];
    int tx = threadIdx.x & 31, ty = threadIdx.x >> 5;
    int bn = blockIdx.z;
    int s0 = blockIdx.x * 32, d0 = blockIdx.y * 32;
    const float* src = t + (long)bn * (S * DD);
    #pragma unroll
    for (int i = 0; i < 4; i++)
        tile[ty + 8 * i][tx] = src[(long)(s0 + ty + 8 * i) * 256 + d0 + tx];
    __syncthreads();
    float* dst = tT + (long)bn * (S * DD);
    int ps = kperm(s0 + tx);
    #pragma unroll
    for (int i = 0; i < 4; i++)
        dst[(long)(d0 + ty + 8 * i) * 1024 + ps] = tf32r(tile[tx][ty + 8 * i]);
}

// ---------------------------------------------------------------------------
// LN producing bf16 hi/lo (bperm) — feeds score GEMM
// ---------------------------------------------------------------------------
__global__ __launch_bounds__(256)
void ln_split_k(const float* __restrict__ in, __nv_bfloat16* __restrict__ oh,
                __nv_bfloat16* __restrict__ ol,
                const float* __restrict__ gam, const float* __restrict__ bet)
{
    int warp = (blockIdx.x * blockDim.x + threadIdx.x) >> 5;
    int lane = threadIdx.x & 31;
    const float* x = in + (long)warp * DD;

    float v[8], s = 0.f, ss = 0.f;
    #pragma unroll
    for (int i = 0; i < 8; i++) {
        v[i] = x[lane + 32 * i];
        s += v[i]; ss += v[i] * v[i];
    }
    #pragma unroll
    for (int o = 16; o; o >>= 1) {
        s  += __shfl_xor_sync(0xffffffffu, s,  o);
        ss += __shfl_xor_sync(0xffffffffu, ss, o);
    }
    float mu = s * (1.f / DD);
    float var = ss * (1.f / DD) - mu * mu;
    float rs = rsqrtf(var + 1e-5f);

    __nv_bfloat16* oh_ = oh + (long)warp * DD;
    __nv_bfloat16* ol_ = ol + (long)warp * DD;
    #pragma unroll
    for (int i = 0; i < 8; i++) {
        int c = lane + 32 * i;
        int pc = bperm(c);
        float y = (v[i] - mu) * rs * gam[c] + bet[c];
        bf16split(y, oh_[pc], ol_[pc]);
    }
}

// LN producing fp32 tf32-rounded (kperm) — feeds FFN1 (MODE 0)
__global__ __launch_bounds__(256)
void ln_plain_k(const float* __restrict__ in, float* __restrict__ out,
                const float* __restrict__ gam, const float* __restrict__ bet)
{
    int warp = (blockIdx.x * blockDim.x + threadIdx.x) >> 5;
    int lane = threadIdx.x & 31;
    const float* x = in + (long)warp * DD;

    float v[8], s = 0.f, ss = 0.f;
    #pragma unroll
    for (int i = 0; i < 8; i++) {
        v[i] = x[lane + 32 * i];
        s += v[i]; ss += v[i] * v[i];
    }
    #pragma unroll
    for (int o = 16; o; o >>= 1) {
        s  += __shfl_xor_sync(0xffffffffu, s,  o);
        ss += __shfl_xor_sync(0xffffffffu, ss, o);
    }
    float mu = s * (1.f / DD);
    float var = ss * (1.f / DD) - mu * mu;
    float rs = rsqrtf(var + 1e-5f);

    float* o_ = out + (long)warp * DD;
    #pragma unroll
    for (int i = 0; i < 8; i++) {
        int c = lane + 32 * i;
        o_[kperm(c)] = tf32r((v[i] - mu) * rs * gam[c] + bet[c]);
    }
}

// ---------------------------------------------------------------------------
__global__ __launch_bounds__(256)
void softmax_k(float* __restrict__ p)
{
    int warp = (blockIdx.x * blockDim.x + threadIdx.x) >> 5;
    int lane = threadIdx.x & 31;
    int q = warp & (S - 1);
    float* row = p + (long)warp * S;

    float v[32], mx = -3.4e38f;
    #pragma unroll
    for (int i = 0; i < 32; i++) {
        int col = lane + 32 * i;
        v[i] = (col <= q) ? row[col] : -3.4e38f;
        mx = fmaxf(mx, v[i]);
    }
    #pragma unroll
    for (int o = 16; o; o >>= 1) mx = fmaxf(mx, __shfl_xor_sync(0xffffffffu, mx, o));

    float sum = 0.f;
    #pragma unroll
    for (int i = 0; i < 32; i++) {
        int col = lane + 32 * i;
        v[i] = (col <= q) ? expf(v[i] - mx) : 0.f;
        sum += v[i];
    }
    #pragma unroll
    for (int o = 16; o; o >>= 1) sum += __shfl_xor_sync(0xffffffffu, sum, o);
    float inv = 1.f / sum;

    int kend = ((q >> 7) + 1) << 7;
    #pragma unroll
    for (int i = 0; i < 32; i++) {
        int col = lane + 32 * i;
        if (col < kend) row[kperm(col)] = tf32r(v[i] * inv);
    }
}

// ---------------------------------------------------------------------------
extern "C" void kernel_launch(void* const* d_in, const int* in_sizes, int n_in,
                              void* d_out, int out_size)
{
    (void)in_sizes; (void)n_in; (void)out_size;
    const float* buffer = (const float*)d_in[0];
    const float* W_in   = (const float*)d_in[1];
    const float* ln1_g  = (const float*)d_in[2];
    const float* ln1_b  = (const float*)d_in[3];
    const float* ln2_g  = (const float*)d_in[4];
    const float* ln2_b  = (const float*)d_in[5];
    const float* W1     = (const float*)d_in[6];
    const float* W2     = (const float*)d_in[7];
    const float* W_out  = (const float*)d_in[8];
    float* out = (float*)d_out;

    __nv_bfloat16 *xth, *xtl, *tnh, *tnl, *ybh, *ybl, *wih, *wil, *woh, *wol;
    float *t, *tT, *hn, *p, *att, *hf, *w1p, *w2p;
    cudaGetSymbolAddress((void**)&xth, g_xth);
    cudaGetSymbolAddress((void**)&xtl, g_xtl);
    cudaGetSymbolAddress((void**)&tnh, g_tnh);
    cudaGetSymbolAddress((void**)&tnl, g_tnl);
    cudaGetSymbolAddress((void**)&ybh, g_ybh);
    cudaGetSymbolAddress((void**)&ybl, g_ybl);
    cudaGetSymbolAddress((void**)&wih, g_wih);
    cudaGetSymbolAddress((void**)&wil, g_wil);
    cudaGetSymbolAddress((void**)&woh, g_woh);
    cudaGetSymbolAddress((void**)&wol, g_wol);
    cudaGetSymbolAddress((void**)&t,   g_t);
    cudaGetSymbolAddress((void**)&tT,  g_tT);
    cudaGetSymbolAddress((void**)&hn,  g_hn);
    cudaGetSymbolAddress((void**)&p,   g_p);
    cudaGetSymbolAddress((void**)&att, g_att);
    cudaGetSymbolAddress((void**)&hf,  g_hf);
    cudaGetSymbolAddress((void**)&w1p, g_w1p);
    cudaGetSymbolAddress((void**)&w2p, g_w2p);

    const long sT = (long)S * DD;
    const long sP = (long)S * S;
    const long sH = (long)S * FD;
    const long sX = (long)S * CD;

    const int smem_b = 3 * 6144 * 4;   // 73728 B
    cudaFuncSetAttribute(mma_gemm<1, 0, 0>, cudaFuncAttributeMaxDynamicSharedMemorySize, smem_b);
    cudaFuncSetAttribute(mma_gemm<1, 0, 1>, cudaFuncAttributeMaxDynamicSharedMemorySize, smem_b);
    cudaFuncSetAttribute(mma_gemm<1, 3, 0>, cudaFuncAttributeMaxDynamicSharedMemorySize, smem_b);
    cudaFuncSetAttribute(mma_gemm<0, 2, 2>, cudaFuncAttributeMaxDynamicSharedMemorySize, smem_b);
    cudaFuncSetAttribute(mma_gemm<0, 1, 0>, cudaFuncAttributeMaxDynamicSharedMemorySize, smem_b);
    cudaFuncSetAttribute(mma_gemm<0, 4, 0>, cudaFuncAttributeMaxDynamicSharedMemorySize, smem_b);

    // weight prep
    {
        const int ntot = DD * CD + CD * DD + FD * DD + DD * FD;
        wprep_k<<<(ntot + 255) / 256, 256>>>(W_in, W_out, W1, W2,
                                             wih, wil, woh, wol, w1p, w2p);
    }

    // 0) transpose x -> xt bf16 hi/lo (bperm c)
    transpose_x_k<<<dim3(32, 2, BNT), 256>>>(buffer, xth, xtl);

    // 1) t = xt . W_in^T   (bf16 2-split)
    mma_gemm<1, 0, 0><<<dim3(4, 8, BNT), 256, smem_b>>>(
        xth, xtl, sX, CD,  wih, wil, 0, CD,
        t, nullptr, sT, DD,  nullptr, 0, nullptr, CD);

    // 2) tn = LN1(t) -> bf16 hi/lo (bperm d)
    ln_split_k<<<(BNT * S) / 8, 256>>>(t, tnh, tnl, ln1_g, ln1_b);

    // 3) scores = tn . tn^T  (bf16 2-split, causal tile skip)
    mma_gemm<1, 0, 1><<<dim3(16, 8, BNT), 256, smem_b>>>(
        tnh, tnl, sT, DD,  tnh, tnl, sT, DD,
        p, nullptr, sP, S,  nullptr, 0, nullptr, DD);

    // 4) softmax (tf32-rounded, kperm cols)
    softmax_k<<<(BNT * S) / 8, 256>>>(p);

    // 5) transpose t -> tT (kperm s, tf32-rounded)
    transpose_t_k<<<dim3(32, 8, BNT), 256>>>(t, tT);

    // 6) att = p . t + t    (tf32 single, K limited)
    mma_gemm<0, 2, 2><<<dim3(4, 8, BNT), 256, smem_b>>>(
        p, nullptr, sP, S,  tT, nullptr, sT, S,
        att, nullptr, sT, DD,  t, sT, nullptr, S);

    // 7) hn = LN2(att)  (tf32-rounded, kperm d)
    ln_plain_k<<<(BNT * S) / 8, 256>>>(att, hn, ln2_g, ln2_b);

    // 8) hf = relu(hn . W1^T)  (tf32 single; rna+kperm f output)
    mma_gemm<0, 1, 0><<<dim3(8, 8, BNT), 256, smem_b>>>(
        hn, nullptr, sT, DD,  w1p, nullptr, 0, DD,
        hf, nullptr, sH, FD,  nullptr, 0, nullptr, DD);

    // 9) y = hf . W2^T + t  -> bf16 hi/lo (bperm d)
    mma_gemm<0, 4, 0><<<dim3(4, 8, BNT), 256, smem_b>>>(
        hf, nullptr, sH, FD,  w2p, nullptr, 0, FD,
        (float*)ybh, (float*)ybl, sT, DD,  t, sT, nullptr, FD);

    // 10) out = y . W_out^T (bf16 2-split, scatter epilogue)
    mma_gemm<1, 3, 0><<<dim3(1, 8, BNT), 256, smem_b>>>(
        ybh, ybl, sT, DD,  woh, wol, 0, DD,
        nullptr, nullptr, 0, 0,  nullptr, 0, out, DD);
}

// round 8
// speedup vs baseline: 2.2507x; 1.3498x over previous
#include <cuda_runtime.h>
#include <cuda_bf16.h>
#include <cuda_fp16.h>
#include <cstdint>

#define S    1024
#define CD   64
#define DD   256
#define FD   512
#define BNT  32

// bf16 buffers (2-term split operands)
__device__ __align__(256) __nv_bfloat16 g_xth[BNT * S * CD];
__device__ __align__(256) __nv_bfloat16 g_xtl[BNT * S * CD];
__device__ __align__(256) __nv_bfloat16 g_tnh[BNT * S * DD];
__device__ __align__(256) __nv_bfloat16 g_tnl[BNT * S * DD];
__device__ __align__(256) __nv_bfloat16 g_ybh[BNT * S * DD];
__device__ __align__(256) __nv_bfloat16 g_ybl[BNT * S * DD];
__device__ __align__(256) __nv_bfloat16 g_wih[DD * CD];
__device__ __align__(256) __nv_bfloat16 g_wil[DD * CD];
__device__ __align__(256) __nv_bfloat16 g_woh[CD * DD];
__device__ __align__(256) __nv_bfloat16 g_wol[CD * DD];
// fp16 buffers (single-pass operands)
__device__ __align__(256) __half g_ph [(long)BNT * S * S];   // normalized p
__device__ __align__(256) __half g_tTh[BNT * S * DD];        // t transposed [d][s]
__device__ __align__(256) __half g_hnh[BNT * S * DD];        // LN2 out
__device__ __align__(256) __half g_hfh[BNT * S * FD];        // FFN1 out
__device__ __align__(256) __half g_w1h[FD * DD];
__device__ __align__(256) __half g_w2h[DD * FD];
// fp32 buffers
__device__ __align__(256) float g_t  [BNT * S * DD];
__device__ __align__(256) float g_p  [(long)BNT * S * S];    // raw scores
__device__ __align__(256) float g_att[BNT * S * DD];

// ---------------------------------------------------------------------------
// bf16/fp16 k-perm within 32: chunk=(k>>1)&3, pos=((k>>3)&3)*2+(k&1)
__device__ __forceinline__ int bperm(int k) {
    return (k & ~31) | (((k >> 1) & 3) << 3) | (((k >> 3) & 3) << 1) | (k & 1);
}

#define MMA_BF16(d, a0, a1, a2, a3, b0, b1)                                   \
    asm volatile("mma.sync.aligned.m16n8k16.row.col.f32.bf16.bf16.f32 "       \
                 "{%0,%1,%2,%3}, {%4,%5,%6,%7}, {%8,%9}, {%0,%1,%2,%3};\n"    \
                 : "+f"(d[0]), "+f"(d[1]), "+f"(d[2]), "+f"(d[3])             \
                 : "r"(a0), "r"(a1), "r"(a2), "r"(a3), "r"(b0), "r"(b1))

#define MMA_F16(d, a0, a1, a2, a3, b0, b1)                                    \
    asm volatile("mma.sync.aligned.m16n8k16.row.col.f32.f16.f16.f32 "         \
                 "{%0,%1,%2,%3}, {%4,%5,%6,%7}, {%8,%9}, {%0,%1,%2,%3};\n"    \
                 : "+f"(d[0]), "+f"(d[1]), "+f"(d[2]), "+f"(d[3])             \
                 : "r"(a0), "r"(a1), "r"(a2), "r"(a3), "r"(b0), "r"(b1))

#define UF(x) __float_as_uint(x)

#define CP16(dst, src)                                                        \
    asm volatile("cp.async.cg.shared.global [%0], [%1], 16;\n"                \
                 :: "r"(dst), "l"(src))

__device__ __forceinline__ int sw_addr(int m, int q) {
    return m * 16 + (((q ^ ((m >> 1) & 3)) & 3) << 2);
}

__device__ __forceinline__ void bf16split(float v, __nv_bfloat16& h, __nv_bfloat16& l) {
    h = __float2bfloat16_rn(v);
    l = __float2bfloat16_rn(v - __bfloat162float(h));
}

// ---------------------------------------------------------------------------
// cp.async 3-stage pipelined MMA GEMM. 16-bit operands, bperm k-layout.
// MODE 0: fp16 single-pass, BK=64 (stage: A0/B0 = k[0:32), A1/B1 = k[32:64))
// MODE 1: bf16 2-term split, BK=32 (A1/B1 = lo parts)
// EPI  : 0 fp32 store, 1 relu -> fp16 bperm-col store, 2 +R fp32 store,
//        3 scatter to out layout, 4 +R -> bf16 hi/lo split bperm-col
// CAUSAL: 1 tile skip (scores), 2 K limited to m0+128 (P@V)
// Stage = 6144 words: [A0:0..2047][B0:2048..3071][A1:3072..5119][B1:5120..6143]
// ---------------------------------------------------------------------------
template<int MODE, int EPI, int CAUSAL>
__global__ __launch_bounds__(256, 2)
void mma_gemm(const void* __restrict__ A, const void* __restrict__ Al_,
              long sAbn, int lda,
              const void* __restrict__ B, const void* __restrict__ Bl_,
              long sBbn, int ldb,
              float* __restrict__ C, float* __restrict__ C2, long sCbn, int ldc,
              const float* __restrict__ R, long sRbn,
              float* __restrict__ Op, int K)
{
    const int bx = blockIdx.x, by = blockIdx.y, bz = blockIdx.z;
    if (CAUSAL == 1 && bx > 2 * by + 1) return;

    constexpr int SS = 6144;   // words per stage
    extern __shared__ __align__(16) float sh[];

    const int tid = threadIdx.x;
    const int w = tid >> 5, l = tid & 31;
    const int warp_m = (w & 3) * 32, warp_n = (w >> 2) * 32;
    const int g = l >> 2, cc = l & 3;
    const int m0 = by * 128, n0 = bx * 64;

    const char* Abp  = (const char*)A + (long)bz * sAbn * 2;
    const char* Bbp  = (const char*)B + (long)bz * sBbn * 2;
    const char* Ablp = (MODE == 1) ? ((const char*)Al_ + (long)bz * sAbn * 2) : nullptr;
    const char* Bblp = (MODE == 1) ? ((const char*)Bl_ + (long)bz * sBbn * 2) : nullptr;

    int Keff = K;
    if (CAUSAL == 2) { int lim = m0 + 128; if (lim < Keff) Keff = lim; }
    const int nk = (MODE == 0) ? (Keff >> 6) : (Keff >> 5);

    const int am = tid >> 2, aj = tid & 3;
    const long oA0 = ((long)(m0 + am)      * lda + (long)aj * 8) * 2;  // bytes
    const long oA1 = ((long)(m0 + am + 64) * lda + (long)aj * 8) * 2;
    const long oB  = ((long)(n0 + am)      * ldb + (long)aj * 8) * 2;
    const int swz  = ((aj ^ ((am >> 1) & 3)) & 3) << 2;
    const int slA0 = am * 16 + swz;
    const int slA1 = (am + 64) * 16 + swz;
    const int slB  = 2048 + am * 16 + swz;
    const uint32_t sb = (uint32_t)__cvta_generic_to_shared(sh);

    auto issue = [&](int st, int kt) {
        uint32_t s0 = sb + (uint32_t)(st * SS) * 4u;
        if (MODE == 0) {
            long kb = (long)kt * 128;              // 64 fp16 = 128 bytes
            CP16(s0 + slA0 * 4, Abp + oA0 + kb);
            CP16(s0 + slA1 * 4, Abp + oA1 + kb);
            CP16(s0 + slB  * 4, Bbp + oB  + kb);
            CP16(s0 + (slA0 + 3072) * 4, Abp + oA0 + kb + 64);
            CP16(s0 + (slA1 + 3072) * 4, Abp + oA1 + kb + 64);
            CP16(s0 + (slB  + 3072) * 4, Bbp + oB  + kb + 64);
        } else {
            long kb = (long)kt * 64;               // 32 bf16 = 64 bytes
            CP16(s0 + slA0 * 4, Abp + oA0 + kb);
            CP16(s0 + slA1 * 4, Abp + oA1 + kb);
            CP16(s0 + slB  * 4, Bbp + oB  + kb);
            CP16(s0 + (slA0 + 3072) * 4, Ablp + oA0 + kb);
            CP16(s0 + (slA1 + 3072) * 4, Ablp + oA1 + kb);
            CP16(s0 + (slB  + 3072) * 4, Bblp + oB  + kb);
        }
        asm volatile("cp.async.commit_group;\n" ::);
    };

    float acc[2][4][4] = {};

    issue(0, 0);
    if (nk > 1) issue(1, 1);
    else        asm volatile("cp.async.commit_group;\n" ::);

    for (int kt = 0; kt < nk; kt++) {
        asm volatile("cp.async.wait_group 1;\n" ::);
        __syncthreads();
        if (kt + 2 < nk) issue((kt + 2) % 3, kt + 2);
        else             asm volatile("cp.async.commit_group;\n" ::);

        const float* s0A = sh + (kt % 3) * SS;
        const float* s0B = s0A + 2048;
        const float* s1A = s0A + 3072;
        const float* s1B = s0A + 5120;

        float4 Ah[2][2], Bh[4], Al[2][2], Bl[4];
        #pragma unroll
        for (int mi = 0; mi < 2; mi++) {
            int mr = warp_m + mi * 16 + g;
            Ah[mi][0] = *(const float4*)&s0A[sw_addr(mr, cc)];
            Ah[mi][1] = *(const float4*)&s0A[sw_addr(mr + 8, cc)];
            Al[mi][0] = *(const float4*)&s1A[sw_addr(mr, cc)];
            Al[mi][1] = *(const float4*)&s1A[sw_addr(mr + 8, cc)];
        }
        #pragma unroll
        for (int nj = 0; nj < 4; nj++) {
            int nr = warp_n + nj * 8 + g;
            Bh[nj] = *(const float4*)&s0B[sw_addr(nr, cc)];
            Bl[nj] = *(const float4*)&s1B[sw_addr(nr, cc)];
        }

        #pragma unroll
        for (int mi = 0; mi < 2; mi++) {
            #pragma unroll
            for (int nj = 0; nj < 4; nj++) {
                float* d = acc[mi][nj];
                if (MODE == 0) {
                    // fp16 single-pass, k[0:64)
                    MMA_F16(d, UF(Ah[mi][0].x), UF(Ah[mi][1].x), UF(Ah[mi][0].y), UF(Ah[mi][1].y),
                               UF(Bh[nj].x), UF(Bh[nj].y));
                    MMA_F16(d, UF(Ah[mi][0].z), UF(Ah[mi][1].z), UF(Ah[mi][0].w), UF(Ah[mi][1].w),
                               UF(Bh[nj].z), UF(Bh[nj].w));
                    MMA_F16(d, UF(Al[mi][0].x), UF(Al[mi][1].x), UF(Al[mi][0].y), UF(Al[mi][1].y),
                               UF(Bl[nj].x), UF(Bl[nj].y));
                    MMA_F16(d, UF(Al[mi][0].z), UF(Al[mi][1].z), UF(Al[mi][0].w), UF(Al[mi][1].w),
                               UF(Bl[nj].z), UF(Bl[nj].w));
                } else {
                    // bf16 2-term split: hh + h*lo + lo*h over k[0:32)
                    MMA_BF16(d, UF(Ah[mi][0].x), UF(Ah[mi][1].x), UF(Ah[mi][0].y), UF(Ah[mi][1].y),
                                UF(Bh[nj].x), UF(Bh[nj].y));
                    MMA_BF16(d, UF(Ah[mi][0].x), UF(Ah[mi][1].x), UF(Ah[mi][0].y), UF(Ah[mi][1].y),
                                UF(Bl[nj].x), UF(Bl[nj].y));
                    MMA_BF16(d, UF(Al[mi][0].x), UF(Al[mi][1].x), UF(Al[mi][0].y), UF(Al[mi][1].y),
                                UF(Bh[nj].x), UF(Bh[nj].y));
                    MMA_BF16(d, UF(Ah[mi][0].z), UF(Ah[mi][1].z), UF(Ah[mi][0].w), UF(Ah[mi][1].w),
                                UF(Bh[nj].z), UF(Bh[nj].w));
                    MMA_BF16(d, UF(Ah[mi][0].z), UF(Ah[mi][1].z), UF(Ah[mi][0].w), UF(Ah[mi][1].w),
                                UF(Bl[nj].z), UF(Bl[nj].w));
                    MMA_BF16(d, UF(Al[mi][0].z), UF(Al[mi][1].z), UF(Al[mi][0].w), UF(Al[mi][1].w),
                                UF(Bh[nj].z), UF(Bh[nj].w));
                }
            }
        }
    }

    // ---- epilogue ----
    if (EPI == 3) {
        const int b = bz >> 3, n = bz & 7;
        #pragma unroll
        for (int mi = 0; mi < 2; mi++) {
            #pragma unroll
            for (int nj = 0; nj < 4; nj++) {
                int row = m0 + warp_m + mi * 16 + g;
                int col = n0 + warp_n + nj * 8 + 2 * cc;
                Op[((long)(b * 64 + col)     * 8 + n) * 1024 + row]     = acc[mi][nj][0];
                Op[((long)(b * 64 + col + 1) * 8 + n) * 1024 + row]     = acc[mi][nj][1];
                Op[((long)(b * 64 + col)     * 8 + n) * 1024 + row + 8] = acc[mi][nj][2];
                Op[((long)(b * 64 + col + 1) * 8 + n) * 1024 + row + 8] = acc[mi][nj][3];
            }
        }
    } else if (EPI == 1) {
        __half* Cb = (__half*)C + (long)bz * sCbn;
        #pragma unroll
        for (int mi = 0; mi < 2; mi++) {
            #pragma unroll
            for (int nj = 0; nj < 4; nj++) {
                int row = m0 + warp_m + mi * 16 + g;
                int col = n0 + warp_n + nj * 8 + 2 * cc;
                int p0 = bperm(col);             // col even -> bperm(col+1)=p0+1
                *(__half2*)&Cb[(long)row * ldc + p0] =
                    __floats2half2_rn(fmaxf(acc[mi][nj][0], 0.f), fmaxf(acc[mi][nj][1], 0.f));
                *(__half2*)&Cb[(long)(row + 8) * ldc + p0] =
                    __floats2half2_rn(fmaxf(acc[mi][nj][2], 0.f), fmaxf(acc[mi][nj][3], 0.f));
            }
        }
    } else if (EPI == 4) {
        __nv_bfloat16* Cb  = (__nv_bfloat16*)C  + (long)bz * sCbn;
        __nv_bfloat16* C2b = (__nv_bfloat16*)C2 + (long)bz * sCbn;
        const float* Rb = R + (long)bz * sRbn;
        #pragma unroll
        for (int mi = 0; mi < 2; mi++) {
            #pragma unroll
            for (int nj = 0; nj < 4; nj++) {
                int row = m0 + warp_m + mi * 16 + g;
                int col = n0 + warp_n + nj * 8 + 2 * cc;
                int p0 = bperm(col);
                float2 r0 = *(const float2*)(Rb + (long)row * ldc + col);
                float2 r1 = *(const float2*)(Rb + (long)(row + 8) * ldc + col);
                float v[4] = {acc[mi][nj][0] + r0.x, acc[mi][nj][1] + r0.y,
                              acc[mi][nj][2] + r1.x, acc[mi][nj][3] + r1.y};
                __nv_bfloat16 h[4], lo[4];
                #pragma unroll
                for (int q = 0; q < 4; q++) bf16split(v[q], h[q], lo[q]);
                *(__nv_bfloat162*)&Cb [(long)row * ldc + p0]       = __nv_bfloat162(h[0],  h[1]);
                *(__nv_bfloat162*)&Cb [(long)(row + 8) * ldc + p0] = __nv_bfloat162(h[2],  h[3]);
                *(__nv_bfloat162*)&C2b[(long)row * ldc + p0]       = __nv_bfloat162(lo[0], lo[1]);
                *(__nv_bfloat162*)&C2b[(long)(row + 8) * ldc + p0] = __nv_bfloat162(lo[2], lo[3]);
            }
        }
    } else {
        float* Cb = C + (long)bz * sCbn;
        const float* Rb = (EPI == 2) ? (R + (long)bz * sRbn) : nullptr;
        #pragma unroll
        for (int mi = 0; mi < 2; mi++) {
            #pragma unroll
            for (int nj = 0; nj < 4; nj++) {
                int row = m0 + warp_m + mi * 16 + g;
                int col = n0 + warp_n + nj * 8 + 2 * cc;
                float v[4] = {acc[mi][nj][0], acc[mi][nj][1], acc[mi][nj][2], acc[mi][nj][3]};
                if (EPI == 2) {
                    float2 r0 = *(const float2*)(Rb + (long)row * ldc + col);
                    float2 r1 = *(const float2*)(Rb + (long)(row + 8) * ldc + col);
                    v[0] += r0.x; v[1] += r0.y; v[2] += r1.x; v[3] += r1.y;
                }
                *(float2*)(Cb + (long)row * ldc + col)       = make_float2(v[0], v[1]);
                *(float2*)(Cb + (long)(row + 8) * ldc + col) = make_float2(v[2], v[3]);
            }
        }
    }
}

// ---------------------------------------------------------------------------
// Weight prep: W_in/W_out -> bf16 hi/lo (bperm); W1/W2 -> fp16 (bperm)
// ---------------------------------------------------------------------------
__global__ __launch_bounds__(256)
void wprep_k(const float* __restrict__ W_in, const float* __restrict__ W_out,
             const float* __restrict__ W1, const float* __restrict__ W2,
             __nv_bfloat16* __restrict__ wih, __nv_bfloat16* __restrict__ wil,
             __nv_bfloat16* __restrict__ woh, __nv_bfloat16* __restrict__ wol,
             __half* __restrict__ w1h, __half* __restrict__ w2h)
{
    int i = blockIdx.x * 256 + threadIdx.x;
    const int nWi = DD * CD, nWo = CD * DD, nW1 = FD * DD;
    if (i < nWi) {
        int row = i / CD, k = i % CD;
        int o = row * CD + bperm(k);
        bf16split(W_in[i], wih[o], wil[o]);
    } else if (i < nWi + nWo) {
        int j = i - nWi;
        int row = j / DD, k = j % DD;
        int o = row * DD + bperm(k);
        bf16split(W_out[j], woh[o], wol[o]);
    } else if (i < nWi + nWo + nW1) {
        int j = i - nWi - nWo;
        int row = j / DD, k = j % DD;
        w1h[row * DD + bperm(k)] = __float2half_rn(W1[j]);
    } else {
        int j = i - nWi - nWo - nW1;
        if (j < DD * FD) {
            int row = j / FD, k = j % FD;
            w2h[row * FD + bperm(k)] = __float2half_rn(W2[j]);
        }
    }
}

__global__ __launch_bounds__(256)
void transpose_x_k(const float* __restrict__ x, __nv_bfloat16* __restrict__ xth,
                   __nv_bfloat16* __restrict__ xtl)
{
    __shared__ float tile[32][33];
    int tx = threadIdx.x & 31, ty = threadIdx.x >> 5;
    int bn = blockIdx.z, b = bn >> 3, n = bn & 7;
    int s0 = blockIdx.x * 32, c0 = blockIdx.y * 32;
    const float* src = x + ((long)b * 64 * 8 + n) * 1024;
    #pragma unroll
    for (int i = 0; i < 4; i++)
        tile[ty + 8 * i][tx] = src[(long)(c0 + ty + 8 * i) * 8192 + s0 + tx];
    __syncthreads();
    __nv_bfloat16* dh = xth + (long)bn * (S * CD);
    __nv_bfloat16* dl = xtl + (long)bn * (S * CD);
    int pc = bperm(c0 + tx);
    #pragma unroll
    for (int i = 0; i < 4; i++) {
        long idx = (long)(s0 + ty + 8 * i) * 64 + pc;
        bf16split(tile[tx][ty + 8 * i], dh[idx], dl[idx]);
    }
}

// t -> tT fp16 [d][s], bperm on s
__global__ __launch_bounds__(256)
void transpose_t_k(const float* __restrict__ t, __half* __restrict__ tT)
{
    __shared__ float tile[32][33];
    int tx = threadIdx.x & 31, ty = threadIdx.x >> 5;
    int bn = blockIdx.z;
    int s0 = blockIdx.x * 32, d0 = blockIdx.y * 32;
    const float* src = t + (long)bn * (S * DD);
    #pragma unroll
    for (int i = 0; i < 4; i++)
        tile[ty + 8 * i][tx] = src[(long)(s0 + ty + 8 * i) * 256 + d0 + tx];
    __syncthreads();
    __half* dst = tT + (long)bn * (S * DD);
    int ps = bperm(s0 + tx);
    #pragma unroll
    for (int i = 0; i < 4; i++)
        dst[(long)(d0 + ty + 8 * i) * 1024 + ps] = __float2half_rn(tile[tx][ty + 8 * i]);
}

// ---------------------------------------------------------------------------
// LN producing bf16 hi/lo (bperm) — feeds score GEMM
// ---------------------------------------------------------------------------
__global__ __launch_bounds__(256)
void ln_split_k(const float* __restrict__ in, __nv_bfloat16* __restrict__ oh,
                __nv_bfloat16* __restrict__ ol,
                const float* __restrict__ gam, const float* __restrict__ bet)
{
    int warp = (blockIdx.x * blockDim.x + threadIdx.x) >> 5;
    int lane = threadIdx.x & 31;
    const float* x = in + (long)warp * DD;

    float v[8], s = 0.f, ss = 0.f;
    #pragma unroll
    for (int i = 0; i < 8; i++) {
        v[i] = x[lane + 32 * i];
        s += v[i]; ss += v[i] * v[i];
    }
    #pragma unroll
    for (int o = 16; o; o >>= 1) {
        s  += __shfl_xor_sync(0xffffffffu, s,  o);
        ss += __shfl_xor_sync(0xffffffffu, ss, o);
    }
    float mu = s * (1.f / DD);
    float var = ss * (1.f / DD) - mu * mu;
    float rs = rsqrtf(var + 1e-5f);

    __nv_bfloat16* oh_ = oh + (long)warp * DD;
    __nv_bfloat16* ol_ = ol + (long)warp * DD;
    #pragma unroll
    for (int i = 0; i < 8; i++) {
        int c = lane + 32 * i;
        int pc = bperm(c);
        float y = (v[i] - mu) * rs * gam[c] + bet[c];
        bf16split(y, oh_[pc], ol_[pc]);
    }
}

// LN producing fp16 (bperm) — feeds FFN1 (MODE 0)
__global__ __launch_bounds__(256)
void ln_half_k(const float* __restrict__ in, __half* __restrict__ out,
               const float* __restrict__ gam, const float* __restrict__ bet)
{
    int warp = (blockIdx.x * blockDim.x + threadIdx.x) >> 5;
    int lane = threadIdx.x & 31;
    const float* x = in + (long)warp * DD;

    float v[8], s = 0.f, ss = 0.f;
    #pragma unroll
    for (int i = 0; i < 8; i++) {
        v[i] = x[lane + 32 * i];
        s += v[i]; ss += v[i] * v[i];
    }
    #pragma unroll
    for (int o = 16; o; o >>= 1) {
        s  += __shfl_xor_sync(0xffffffffu, s,  o);
        ss += __shfl_xor_sync(0xffffffffu, ss, o);
    }
    float mu = s * (1.f / DD);
    float var = ss * (1.f / DD) - mu * mu;
    float rs = rsqrtf(var + 1e-5f);

    __half* o_ = out + (long)warp * DD;
    #pragma unroll
    for (int i = 0; i < 8; i++) {
        int c = lane + 32 * i;
        o_[bperm(c)] = __float2half_rn((v[i] - mu) * rs * gam[c] + bet[c]);
    }
}

// ---------------------------------------------------------------------------
// softmax: reads fp32 scores, writes fp16 normalized p (bperm cols)
// ---------------------------------------------------------------------------
__global__ __launch_bounds__(256)
void softmax_k(const float* __restrict__ p, __half* __restrict__ ph)
{
    int warp = (blockIdx.x * blockDim.x + threadIdx.x) >> 5;
    int lane = threadIdx.x & 31;
    int q = warp & (S - 1);
    const float* row = p + (long)warp * S;
    __half* rowh = ph + (long)warp * S;

    float v[32], mx = -3.4e38f;
    #pragma unroll
    for (int i = 0; i < 32; i++) {
        int col = lane + 32 * i;
        v[i] = (col <= q) ? row[col] : -3.4e38f;
        mx = fmaxf(mx, v[i]);
    }
    #pragma unroll
    for (int o = 16; o; o >>= 1) mx = fmaxf(mx, __shfl_xor_sync(0xffffffffu, mx, o));

    float sum = 0.f;
    #pragma unroll
    for (int i = 0; i < 32; i++) {
        int col = lane + 32 * i;
        v[i] = (col <= q) ? expf(v[i] - mx) : 0.f;
        sum += v[i];
    }
    #pragma unroll
    for (int o = 16; o; o >>= 1) sum += __shfl_xor_sync(0xffffffffu, sum, o);
    float inv = 1.f / sum;

    int kend = ((q >> 7) + 1) << 7;
    #pragma unroll
    for (int i = 0; i < 32; i++) {
        int col = lane + 32 * i;
        if (col < kend) rowh[bperm(col)] = __float2half_rn(v[i] * inv);
    }
}

// ---------------------------------------------------------------------------
extern "C" void kernel_launch(void* const* d_in, const int* in_sizes, int n_in,
                              void* d_out, int out_size)
{
    (void)in_sizes; (void)n_in; (void)out_size;
    const float* buffer = (const float*)d_in[0];
    const float* W_in   = (const float*)d_in[1];
    const float* ln1_g  = (const float*)d_in[2];
    const float* ln1_b  = (const float*)d_in[3];
    const float* ln2_g  = (const float*)d_in[4];
    const float* ln2_b  = (const float*)d_in[5];
    const float* W1     = (const float*)d_in[6];
    const float* W2     = (const float*)d_in[7];
    const float* W_out  = (const float*)d_in[8];
    float* out = (float*)d_out;

    __nv_bfloat16 *xth, *xtl, *tnh, *tnl, *ybh, *ybl, *wih, *wil, *woh, *wol;
    __half *ph, *tTh, *hnh, *hfh, *w1h, *w2h;
    float *t, *p, *att;
    cudaGetSymbolAddress((void**)&xth, g_xth);
    cudaGetSymbolAddress((void**)&xtl, g_xtl);
    cudaGetSymbolAddress((void**)&tnh, g_tnh);
    cudaGetSymbolAddress((void**)&tnl, g_tnl);
    cudaGetSymbolAddress((void**)&ybh, g_ybh);
    cudaGetSymbolAddress((void**)&ybl, g_ybl);
    cudaGetSymbolAddress((void**)&wih, g_wih);
    cudaGetSymbolAddress((void**)&wil, g_wil);
    cudaGetSymbolAddress((void**)&woh, g_woh);
    cudaGetSymbolAddress((void**)&wol, g_wol);
    cudaGetSymbolAddress((void**)&ph,  g_ph);
    cudaGetSymbolAddress((void**)&tTh, g_tTh);
    cudaGetSymbolAddress((void**)&hnh, g_hnh);
    cudaGetSymbolAddress((void**)&hfh, g_hfh);
    cudaGetSymbolAddress((void**)&w1h, g_w1h);
    cudaGetSymbolAddress((void**)&w2h, g_w2h);
    cudaGetSymbolAddress((void**)&t,   g_t);
    cudaGetSymbolAddress((void**)&p,   g_p);
    cudaGetSymbolAddress((void**)&att, g_att);

    const long sT = (long)S * DD;
    const long sP = (long)S * S;
    const long sH = (long)S * FD;
    const long sX = (long)S * CD;

    const int smem_b = 3 * 6144 * 4;   // 73728 B
    cudaFuncSetAttribute(mma_gemm<1, 0, 0>, cudaFuncAttributeMaxDynamicSharedMemorySize, smem_b);
    cudaFuncSetAttribute(mma_gemm<1, 0, 1>, cudaFuncAttributeMaxDynamicSharedMemorySize, smem_b);
    cudaFuncSetAttribute(mma_gemm<1, 3, 0>, cudaFuncAttributeMaxDynamicSharedMemorySize, smem_b);
    cudaFuncSetAttribute(mma_gemm<0, 2, 2>, cudaFuncAttributeMaxDynamicSharedMemorySize, smem_b);
    cudaFuncSetAttribute(mma_gemm<0, 1, 0>, cudaFuncAttributeMaxDynamicSharedMemorySize, smem_b);
    cudaFuncSetAttribute(mma_gemm<0, 4, 0>, cudaFuncAttributeMaxDynamicSharedMemorySize, smem_b);

    // weight prep
    {
        const int ntot = DD * CD + CD * DD + FD * DD + DD * FD;
        wprep_k<<<(ntot + 255) / 256, 256>>>(W_in, W_out, W1, W2,
                                             wih, wil, woh, wol, w1h, w2h);
    }

    // 0) transpose x -> xt bf16 hi/lo (bperm c)
    transpose_x_k<<<dim3(32, 2, BNT), 256>>>(buffer, xth, xtl);

    // 1) t = xt . W_in^T   (bf16 2-split)
    mma_gemm<1, 0, 0><<<dim3(4, 8, BNT), 256, smem_b>>>(
        xth, xtl, sX, CD,  wih, wil, 0, CD,
        t, nullptr, sT, DD,  nullptr, 0, nullptr, CD);

    // 2) tn = LN1(t) -> bf16 hi/lo (bperm d)
    ln_split_k<<<(BNT * S) / 8, 256>>>(t, tnh, tnl, ln1_g, ln1_b);

    // 3) scores = tn . tn^T  (bf16 2-split, causal tile skip) -> fp32 p
    mma_gemm<1, 0, 1><<<dim3(16, 8, BNT), 256, smem_b>>>(
        tnh, tnl, sT, DD,  tnh, tnl, sT, DD,
        p, nullptr, sP, S,  nullptr, 0, nullptr, DD);

    // 4) softmax -> fp16 p (bperm cols)
    softmax_k<<<(BNT * S) / 8, 256>>>(p, ph);

    // 5) transpose t -> tT fp16 (bperm s)
    transpose_t_k<<<dim3(32, 8, BNT), 256>>>(t, tTh);

    // 6) att = p . t + t    (fp16 single, BK64, K limited)
    mma_gemm<0, 2, 2><<<dim3(4, 8, BNT), 256, smem_b>>>(
        ph, nullptr, sP, S,  tTh, nullptr, sT, S,
        att, nullptr, sT, DD,  t, sT, nullptr, S);

    // 7) hn = LN2(att) -> fp16 (bperm d)
    ln_half_k<<<(BNT * S) / 8, 256>>>(att, hnh, ln2_g, ln2_b);

    // 8) hf = relu(hn . W1^T)  (fp16 single; fp16 bperm-f output)
    mma_gemm<0, 1, 0><<<dim3(8, 8, BNT), 256, smem_b>>>(
        hnh, nullptr, sT, DD,  w1h, nullptr, 0, DD,
        (float*)hfh, nullptr, sH, FD,  nullptr, 0, nullptr, DD);

    // 9) y = hf . W2^T + t  -> bf16 hi/lo (bperm d)
    mma_gemm<0, 4, 0><<<dim3(4, 8, BNT), 256, smem_b>>>(
        hfh, nullptr, sH, FD,  w2h, nullptr, 0, FD,
        (float*)ybh, (float*)ybl, sT, DD,  t, sT, nullptr, FD);

    // 10) out = y . W_out^T (bf16 2-split, scatter epilogue)
    mma_gemm<1, 3, 0><<<dim3(1, 8, BNT), 256, smem_b>>>(
        ybh, ybl, sT, DD,  woh, wol, 0, DD,
        nullptr, nullptr, 0, 0,  nullptr, 0, out, DD);
}